// round 14
// baseline (speedup 1.0000x reference)
#include <cuda_runtime.h>
#include <cuda_bf16.h>
#include <cstdint>
typedef __nv_bfloat16 bf16;

#define INV_DQ4 0.35355339059327373f
#define BB   8
#define ST   2048
#define SMM  1024
#define DDIM 512
#define DHI  1024
#define TOK  16384
#define TOKM 8192
#define PERB (ST*DDIM)

// ---------------- scratch ----------------
__device__ float g_y[TOK*DDIM];
__device__ float g_qkv[TOK*384];
__device__ float g_qx[TOK*128];
__device__ float g_kv[TOKM*256];
__device__ float g_wp[DDIM*384];
__device__ float g_bp[384];
__device__ float g_pm[BB*8*128], g_pz[BB*8*128];
__device__ float g_qm[BB*128], g_qz[BB*128];
__device__ float g_km[BB*128], g_kz[BB*128];
__device__ float g_bm[16*4096];
__device__ float g_bmp[16*8*4096];
__device__ float g_part[BB*32*2];
__device__ float g_stat[BB*2];
__device__ bf16  g_ah[DHI*ST],  g_al[DHI*ST];      // D1^T/D2^T hi/lo
__device__ bf16  g_bh[384*DDIM], g_bl[384*DDIM];   // small weights hi/lo
__device__ bf16  g_zh[TOK*128],  g_zl[TOK*128];
__device__ bf16  g_hh[TOK*DHI],  g_hl[TOK*DHI];
__device__ bf16  g_w1h[DHI*DDIM], g_w1l[DHI*DDIM];
__device__ bf16  g_w2h[DDIM*DHI], g_w2l[DDIM*DHI];

// W[K][N] fp32 -> T[N][K] bf16 hi/lo
__global__ void tsplit(const float* __restrict__ W, int K, int N,
                       bf16* __restrict__ Th, bf16* __restrict__ Tl)
{
    __shared__ float t[32][33];
    int k0 = blockIdx.x * 32, n0 = blockIdx.y * 32;
    for (int i = threadIdx.y; i < 32; i += 8)
        t[i][threadIdx.x] = W[(long)(k0 + i) * N + n0 + threadIdx.x];
    __syncthreads();
    for (int i = threadIdx.y; i < 32; i += 8) {
        float v = t[threadIdx.x][i];
        bf16 h = __float2bfloat16(v);
        long o = (long)(n0 + i) * K + k0 + threadIdx.x;
        Th[o] = h;
        Tl[o] = __float2bfloat16(v - __bfloat162float(h));
    }
}

// ---------------- bf16-split tensor-core GEMM ----------------
#define MMA_BF16(d, a, b) asm volatile( \
    "mma.sync.aligned.m16n8k16.row.col.f32.bf16.bf16.f32 " \
    "{%0,%1,%2,%3}, {%4,%5,%6,%7}, {%8,%9}, {%0,%1,%2,%3};" \
    : "+f"(d[0]), "+f"(d[1]), "+f"(d[2]), "+f"(d[3]) \
    : "r"(a[0]), "r"(a[1]), "r"(a[2]), "r"(a[3]), "r"(b[0]), "r"(b[1]))

#define LDSM4(R, a) asm volatile( \
    "ldmatrix.sync.aligned.m8n8.x4.shared.b16 {%0,%1,%2,%3}, [%4];" \
    : "=r"((R)[0]), "=r"((R)[1]), "=r"((R)[2]), "=r"((R)[3]) : "r"(a))

__device__ __forceinline__ void cvt8(float4 a, float4 b, uint4& h4, uint4& l4)
{
    float v[8] = {a.x,a.y,a.z,a.w,b.x,b.y,b.z,b.w};
    bf16 h[8], l[8];
    #pragma unroll
    for (int k = 0; k < 8; k++) {
        h[k] = __float2bfloat16(v[k]);
        l[k] = __float2bfloat16(v[k] - __bfloat162float(h[k]));
    }
    h4 = *(uint4*)h; l4 = *(uint4*)l;
}

// C[M,N] = A[M,K] @ B[N,K]^T split-bf16; K%32==0. AF32/BF32: operand is fp32,
// split on the fly. OUT==0: fp32 C (+bias/act/res). OUT==1: bf16 hi/lo (+act).
// Double-buffered dynamic smem: 2*(BM+BN)*128 bytes.
template<int BM, int BN, int WM, int WN, int OUT, int AF32, int BF32>
__global__ void __launch_bounds__((BM/WM)*(BN/WN)*32) mma_gemm(
    const void* __restrict__ Ah_, const void* __restrict__ Al_,
    const void* __restrict__ Bh_, const void* __restrict__ Bl_,
    int K, float* __restrict__ C, bf16* __restrict__ Ch, bf16* __restrict__ Cl,
    int ldc, const float* __restrict__ bias, const float* __restrict__ res, int act)
{
    constexpr int NWN = BN / WN;
    constexpr int NT  = (BM/WM) * NWN * 32;
    constexpr int MT  = WM / 16, NTL = WN / 8;
    extern __shared__ __align__(128) uint4 smem[];
    uint4* sA = smem;                 // 2 stages * BM*8 uint4
    uint4* sB = smem + 2*BM*8;        // 2 stages * BN*8
    const int tid = threadIdx.x, wid = tid >> 5, lane = tid & 31;
    const int wm = wid / NWN, wn = wid % NWN;
    const int lr8 = lane & 7, g = lane >> 3;
    const int lq = lane & 3, lr = lane >> 2;
    const long row0 = (long)blockIdx.y * BM;
    const long col0 = (long)blockIdx.x * BN;
    const uint32_t saA0 = (uint32_t)__cvta_generic_to_shared(sA);
    const uint32_t saB0 = (uint32_t)__cvta_generic_to_shared(sB);
    constexpr int ITA = (BM*4) / NT, ITB = (BN*4) / NT;
    uint4 rah[ITA], ral[ITA], rbh[ITB], rbl[ITB];

    auto ldg = [&](int k0) {
        #pragma unroll
        for (int i = 0; i < ITA; i++) {
            int idx = tid + i*NT;
            long off = (row0 + (idx>>2)) * (long)K + k0 + ((idx&3)<<3);
            if (AF32) {
                const float* A = (const float*)Ah_;
                cvt8(*(const float4*)(A+off), *(const float4*)(A+off+4), rah[i], ral[i]);
            } else {
                rah[i] = *(const uint4*)((const bf16*)Ah_ + off);
                ral[i] = *(const uint4*)((const bf16*)Al_ + off);
            }
        }
        #pragma unroll
        for (int i = 0; i < ITB; i++) {
            int idx = tid + i*NT;
            long off = (col0 + (idx>>2)) * (long)K + k0 + ((idx&3)<<3);
            if (BF32) {
                const float* B = (const float*)Bh_;
                cvt8(*(const float4*)(B+off), *(const float4*)(B+off+4), rbh[i], rbl[i]);
            } else {
                rbh[i] = *(const uint4*)((const bf16*)Bh_ + off);
                rbl[i] = *(const uint4*)((const bf16*)Bl_ + off);
            }
        }
    };
    auto sts = [&](int st) {
        #pragma unroll
        for (int i = 0; i < ITA; i++) {
            int idx = tid + i*NT;
            int row = idx >> 2, c = idx & 3;
            int w = st*BM*8 + row*8 + (c ^ (row & 7));
            sA[w] = rah[i]; sA[w ^ 4] = ral[i];
        }
        #pragma unroll
        for (int i = 0; i < ITB; i++) {
            int idx = tid + i*NT;
            int row = idx >> 2, c = idx & 3;
            int w = st*BN*8 + row*8 + (c ^ (row & 7));
            sB[w] = rbh[i]; sB[w ^ 4] = rbl[i];
        }
    };

    float acc[MT][NTL][4];
    #pragma unroll
    for (int i = 0; i < MT; i++)
        #pragma unroll
        for (int j = 0; j < NTL; j++) {
            acc[i][j][0]=0.f; acc[i][j][1]=0.f; acc[i][j][2]=0.f; acc[i][j][3]=0.f;
        }

    auto compute = [&](int st) {
        uint32_t saA = saA0 + st*BM*128;
        uint32_t saB = saB0 + st*BN*128;
        #pragma unroll
        for (int ks = 0; ks < 2; ks++) {
            uint32_t afh[MT][4], afl[MT][4], bfh[NTL][2], bfl[NTL][2];
            #pragma unroll
            for (int i = 0; i < MT; i++) {
                int row = wm*WM + i*16 + ((g & 1) << 3) + lr8;
                int ch  = (ks << 1) + (g >> 1);
                uint32_t ad = saA + row*128 + ((ch ^ lr8) << 4);
                LDSM4(afh[i], ad);
                LDSM4(afl[i], ad ^ 64u);
            }
            #pragma unroll
            for (int jj = 0; jj < NTL/2; jj++) {
                int row = wn*WN + jj*16 + ((g >> 1) << 3) + lr8;
                int ch  = (ks << 1) + (g & 1);
                uint32_t ad = saB + row*128 + ((ch ^ lr8) << 4);
                uint32_t t[4];
                LDSM4(t, ad);
                bfh[2*jj][0]=t[0]; bfh[2*jj][1]=t[1];
                bfh[2*jj+1][0]=t[2]; bfh[2*jj+1][1]=t[3];
                LDSM4(t, ad ^ 64u);
                bfl[2*jj][0]=t[0]; bfl[2*jj][1]=t[1];
                bfl[2*jj+1][0]=t[2]; bfl[2*jj+1][1]=t[3];
            }
            #pragma unroll
            for (int i = 0; i < MT; i++)
                #pragma unroll
                for (int j = 0; j < NTL; j++) {
                    MMA_BF16(acc[i][j], afh[i], bfh[j]);
                    MMA_BF16(acc[i][j], afh[i], bfl[j]);
                    MMA_BF16(acc[i][j], afl[i], bfh[j]);
                }
        }
    };

    const int nt = K >> 5;
    ldg(0); sts(0); __syncthreads();
    for (int t = 1; t < nt; t++) {
        ldg(t << 5);
        compute((t-1) & 1);
        sts(t & 1);
        __syncthreads();
    }
    compute((nt-1) & 1);

    #pragma unroll
    for (int i = 0; i < MT; i++) {
        int r = (int)row0 + wm*WM + i*16 + lr;
        #pragma unroll
        for (int j = 0; j < NTL; j++) {
            int cb = (int)col0 + wn*WN + j*8 + 2*lq;
            float v[4] = {acc[i][j][0], acc[i][j][1], acc[i][j][2], acc[i][j][3]};
            if (bias) { float b0 = bias[cb], b1 = bias[cb+1];
                        v[0]+=b0; v[1]+=b1; v[2]+=b0; v[3]+=b1; }
            if (act) {
                #pragma unroll
                for (int q = 0; q < 4; q++) v[q] = v[q] / (1.f + __expf(-v[q]));
            }
            long o0 = (long)r*ldc + cb, o1 = o0 + 8L*ldc;
            if (OUT == 0) {
                if (res) { v[0]+=res[o0]; v[1]+=res[o0+1]; v[2]+=res[o1]; v[3]+=res[o1+1]; }
                *(float2*)(C + o0) = make_float2(v[0], v[1]);
                *(float2*)(C + o1) = make_float2(v[2], v[3]);
            } else {
                long oo[4] = {o0, o0+1, o1, o1+1};
                #pragma unroll
                for (int q = 0; q < 4; q++) {
                    bf16 h = __float2bfloat16(v[q]);
                    Ch[oo[q]] = h;
                    Cl[oo[q]] = __float2bfloat16(v[q] - __bfloat162float(h));
                }
            }
        }
    }
}

// ---------------- QKV weight packing ----------------
__global__ void pack_qkv(const float* __restrict__ Wq, const float* __restrict__ Wk,
                         const float* __restrict__ Wv, const float* __restrict__ bq,
                         const float* __restrict__ bk, const float* __restrict__ bv,
                         float* __restrict__ wp, float* __restrict__ bp)
{
    int idx = blockIdx.x * blockDim.x + threadIdx.x;
    if (idx < DDIM * 384) {
        int d = idx / 384, j = idx % 384;
        int p = j >> 7, jj = j & 127;
        int h = jj >> 6, e = jj & 63;
        const float* src = (p == 0) ? Wq : (p == 1) ? Wk : Wv;
        wp[idx] = src[((long)h * DDIM + d) * 64 + e];
    }
    if (idx < 384) {
        int p = idx >> 7, jj = idx & 127;
        const float* sb = (p == 0) ? bq : (p == 1) ? bk : bv;
        bp[idx] = sb[jj];
    }
}

// ---------------- coalesced column softmax stats (online) ----------------
__global__ void colpart(const float* __restrict__ X, int ld, int coloff, int S,
                        int mask, float* __restrict__ pm, float* __restrict__ pz)
{
    int chunk = blockIdx.x, b = blockIdx.y;
    int R = S >> 3;
    int rgrp = threadIdx.x >> 5, cg = threadIdx.x & 31;
    const float* base = X + ((long)(b*S + chunk*R + rgrp))*ld + coloff + cg*4;
    float m[4] = {-1e30f,-1e30f,-1e30f,-1e30f}, z[4] = {0.f,0.f,0.f,0.f};
    int e0 = (cg*4) & 63;
    for (int r = 0; r < R; r += 8) {
        float4 vv = *(const float4*)(base + (long)r*ld);
        int s = chunk*R + rgrp + r;
        float va[4] = {vv.x, vv.y, vv.z, vv.w};
        #pragma unroll
        for (int c = 0; c < 4; c++) {
            if (mask && (e0 + c) > s) continue;
            float val = va[c] * INV_DQ4;
            if (val <= m[c]) z[c] += __expf(val - m[c]);
            else { z[c] = z[c]*__expf(m[c] - val) + 1.f; m[c] = val; }
        }
    }
    __shared__ float sm_[8][128], sz_[8][128];
    #pragma unroll
    for (int c = 0; c < 4; c++) { sm_[rgrp][cg*4+c] = m[c]; sz_[rgrp][cg*4+c] = z[c]; }
    __syncthreads();
    if (threadIdx.x < 128) {
        int col = threadIdx.x;
        float M = -1e30f, Z = 0.f;
        #pragma unroll
        for (int l = 0; l < 8; l++) {
            float mi = sm_[l][col], zi = sz_[l][col];
            if (zi == 0.f) continue;
            if (mi <= M) Z += zi * __expf(mi - M);
            else { Z = Z*__expf(M - mi) + zi; M = mi; }
        }
        pm[(b*8 + chunk)*128 + col] = M;
        pz[(b*8 + chunk)*128 + col] = Z;
    }
}

__global__ void colmerge(const float* __restrict__ pm, const float* __restrict__ pz,
                         float* __restrict__ mo, float* __restrict__ zo)
{
    int b = blockIdx.x, col = threadIdx.x;
    float M = -1e30f, Z = 0.f;
    for (int c = 0; c < 8; c++) {
        float mi = pm[(b*8 + c)*128 + col], zi = pz[(b*8 + c)*128 + col];
        if (zi == 0.f) continue;
        if (mi <= M) Z += zi * __expf(mi - M);
        else { Z = Z*__expf(M - mi) + zi; M = mi; }
    }
    mo[b*128 + col] = M;
    zo[b*128 + col] = Z;
}

// ---------------- Bm partials (exp fused into loader) ----------------
__global__ void __launch_bounds__(256) bmpart(
    const float* __restrict__ Kb, int ldk, int koff,
    const float* __restrict__ Vb, int ldv, int voff,
    int S, const float* __restrict__ km, float* __restrict__ bmp)
{
    int chunk = blockIdx.x, blk = blockIdx.y;   // blk = h*8+b
    int h = blk >> 3, b = blk & 7;
    int R = S >> 3;
    int tid = threadIdx.x;
    int e = tid >> 2, d0 = (tid & 3) * 16;
    __shared__ float Ks[64][64];
    __shared__ float Vs[64][64];
    float acc[16];
    #pragma unroll
    for (int i = 0; i < 16; i++) acc[i] = 0.f;
    const float* kp = Kb + (long)(b*S + chunk*R) * ldk + koff + h*64;
    const float* vp = Vb + (long)(b*S + chunk*R) * ldv + voff + h*64;
    const float* kmb = km + b*128 + h*64;
    for (int t = 0; t < R/64; t++) {
        for (int idx = tid; idx < 64*16; idx += 256) {
            int r = idx >> 4, c4 = (idx & 15) << 2;
            float4 kk = *(const float4*)(kp + (long)(t*64 + r)*ldk + c4);
            float4 mm = *(const float4*)(kmb + c4);
            kk.x = __expf(kk.x*INV_DQ4 - mm.x);
            kk.y = __expf(kk.y*INV_DQ4 - mm.y);
            kk.z = __expf(kk.z*INV_DQ4 - mm.z);
            kk.w = __expf(kk.w*INV_DQ4 - mm.w);
            *(float4*)&Ks[r][c4] = kk;
            *(float4*)&Vs[r][c4] = *(const float4*)(vp + (long)(t*64 + r)*ldv + c4);
        }
        __syncthreads();
        #pragma unroll 4
        for (int s = 0; s < 64; s++) {
            float w = Ks[s][e];
            #pragma unroll
            for (int dd = 0; dd < 16; dd++) acc[dd] += w * Vs[s][d0 + dd];
        }
        __syncthreads();
    }
    float* outp = bmp + ((long)blk*8 + chunk)*4096 + e*64 + d0;
    #pragma unroll
    for (int dd = 0; dd < 16; dd++) outp[dd] = acc[dd];
}

__global__ void bm_reduce(const float* __restrict__ bmp, const float* __restrict__ kz,
                          float* __restrict__ bm)
{
    int gid = blockIdx.x * 256 + threadIdx.x;
    int blk = gid >> 12, r = gid & 4095;
    int h = blk >> 3, b = blk & 7, e = r >> 6;
    float s = 0.f;
    for (int c = 0; c < 8; c++) s += bmp[((long)blk*8 + c)*4096 + r];
    bm[(long)blk*4096 + r] = s / kz[b*128 + h*64 + e];
}

// ---------------- Z = A @ Bm (w precomputed in smem; bf16 hi/lo out) ------
__global__ void __launch_bounds__(256) z_kernel(
    const float* __restrict__ Q, int ldq, const float* __restrict__ bm,
    const float* __restrict__ qm, const float* __restrict__ qz,
    bf16* __restrict__ Zh, bf16* __restrict__ Zl, int mask)
{
    __shared__ float Bs[2][64][64];   // 32 KB
    __shared__ float ws[16][130];     // 8.1 KB
    int tid = threadIdx.x;
    int row0 = blockIdx.x * 16;
    int b = row0 / ST;
    for (int idx = tid; idx < 2048; idx += 256) {
        int hh = idx >> 10, rr = (idx >> 4) & 63, c4 = (idx & 15) << 2;
        *(float4*)&Bs[hh][rr][c4] =
            *(const float4*)(bm + ((long)(hh*BB + b) * 64 + rr) * 64 + c4);
    }
    #pragma unroll
    for (int k = 0; k < 8; k++) {
        int idx = tid + k*256;
        int rid = idx >> 7, je = idx & 127;
        int e = je & 63;
        int s = (row0 + rid) & (ST - 1);
        float w = 0.f;
        if (!(mask && e > s)) {
            float q = Q[(long)(row0 + rid)*ldq + je];
            w = __expf(q*INV_DQ4 - qm[b*128 + je]) / qz[b*128 + je];
        }
        ws[rid][je] = w;
    }
    __syncthreads();
    int rid = tid >> 4, sub = tid & 15;
    int h = sub >> 3, d0 = (sub & 7) * 8;
    float acc[8];
    #pragma unroll
    for (int i = 0; i < 8; i++) acc[i] = 0.f;
    const float* wsr = &ws[rid][h*64];
    for (int e = 0; e < 64; e++) {
        float w = wsr[e];
        const float* bp = &Bs[h][e][d0];
        #pragma unroll
        for (int dd = 0; dd < 8; dd++) acc[dd] += w * bp[dd];
    }
    long o = (long)(row0 + rid) * 128 + h*64 + d0;
    #pragma unroll
    for (int dd = 0; dd < 8; dd++) {
        bf16 hh2 = __float2bfloat16(acc[dd]);
        Zh[o + dd] = hh2;
        Zl[o + dd] = __float2bfloat16(acc[dd] - __bfloat162float(hh2));
    }
}

// ---------------- LayerNorm ----------------
__global__ void ln_part(const float* __restrict__ X, float* __restrict__ part)
{
    int b = blockIdx.y, chunk = blockIdx.x;
    const float4* p = (const float4*)(X + (long)b*PERB) + (long)chunk*8192 + threadIdx.x;
    float s = 0.f, q = 0.f;
    for (int k = 0; k < 32; k++) {
        float4 v = p[(long)k*256];
        s += v.x + v.y + v.z + v.w;
        q += v.x*v.x + v.y*v.y + v.z*v.z + v.w*v.w;
    }
    __shared__ float rs[256], rq[256];
    rs[threadIdx.x] = s; rq[threadIdx.x] = q; __syncthreads();
    for (int st = 128; st > 0; st >>= 1) {
        if (threadIdx.x < st) {
            rs[threadIdx.x] += rs[threadIdx.x + st];
            rq[threadIdx.x] += rq[threadIdx.x + st];
        }
        __syncthreads();
    }
    if (threadIdx.x == 0) {
        part[(b*32 + chunk)*2]     = rs[0];
        part[(b*32 + chunk)*2 + 1] = rq[0];
    }
}

__global__ void ln_final(const float* __restrict__ part, float* __restrict__ stat)
{
    int b = blockIdx.x;
    float s = part[(b*32 + threadIdx.x)*2];
    float q = part[(b*32 + threadIdx.x)*2 + 1];
    for (int o = 16; o > 0; o >>= 1) {
        s += __shfl_down_sync(0xffffffffu, s, o);
        q += __shfl_down_sync(0xffffffffu, q, o);
    }
    if (threadIdx.x == 0) {
        float mean = s / (float)PERB;
        float var  = q / (float)PERB - mean * mean;
        stat[b*2] = mean; stat[b*2 + 1] = rsqrtf(var + 1e-5f);
    }
}

__global__ void ln_apply(const float* __restrict__ X, const float* __restrict__ g,
                         const float* __restrict__ bt, const float* __restrict__ stat,
                         float* __restrict__ out)
{
    long i4  = (long)blockIdx.x * blockDim.x + threadIdx.x;
    long idx = i4 * 4;
    int  b   = (int)(idx / PERB);
    long gi  = idx % PERB;
    float mean = stat[b*2], rstd = stat[b*2 + 1];
    float4 x  = *(const float4*)(X + idx);
    float4 gg = *(const float4*)(g + gi);
    float4 bb = *(const float4*)(bt + gi);
    float4 o;
    o.x = (x.x - mean) * rstd * gg.x + bb.x;
    o.y = (x.y - mean) * rstd * gg.y + bb.y;
    o.z = (x.z - mean) * rstd * gg.z + bb.z;
    o.w = (x.w - mean) * rstd * gg.w + bb.w;
    *(float4*)(out + idx) = o;
}

// ---------------- host orchestration ----------------
#define GSMEM(BM, BN) (2*((BM)+(BN))*128)

extern "C" void kernel_launch(void* const* d_in, const int* in_sizes, int n_in,
                              void* d_out, int out_size)
{
    (void)in_sizes; (void)n_in; (void)out_size;
    const float* mem   = (const float*)d_in[0];
    const float* y_in  = (const float*)d_in[1];
    const float* Wq_sa = (const float*)d_in[2];
    const float* bq_sa = (const float*)d_in[3];
    const float* Wk_sa = (const float*)d_in[4];
    const float* bk_sa = (const float*)d_in[5];
    const float* Wv_sa = (const float*)d_in[6];
    const float* bv_sa = (const float*)d_in[7];
    const float* Wo_sa = (const float*)d_in[8];
    const float* bo_sa = (const float*)d_in[9];
    const float* Wq_x  = (const float*)d_in[10];
    const float* bq_x  = (const float*)d_in[11];
    const float* Wk_x  = (const float*)d_in[12];
    const float* bk_x  = (const float*)d_in[13];
    const float* Wv_x  = (const float*)d_in[14];
    const float* bv_x  = (const float*)d_in[15];
    const float* Wo_x  = (const float*)d_in[16];
    const float* bo_x  = (const float*)d_in[17];
    const float* E1    = (const float*)d_in[18];
    const float* D1    = (const float*)d_in[19];
    const float* E2    = (const float*)d_in[20];
    const float* D2    = (const float*)d_in[21];
    const float* g1    = (const float*)d_in[22];
    const float* b1    = (const float*)d_in[23];
    const float* g2    = (const float*)d_in[24];
    const float* b2    = (const float*)d_in[25];
    const float* g3    = (const float*)d_in[26];
    const float* b3    = (const float*)d_in[27];
    float* out = (float*)d_out;

    float *yp,*qkv,*qx,*kv,*wp,*bp,*pm,*pz,*qm,*qz,*km,*kz,*bm,*bmp,*part,*stat;
    bf16 *ah,*al,*bh,*bl,*zh,*zl,*hh,*hl,*w1h,*w1l,*w2h,*w2l;
    cudaGetSymbolAddress((void**)&yp,   g_y);
    cudaGetSymbolAddress((void**)&qkv,  g_qkv);
    cudaGetSymbolAddress((void**)&qx,   g_qx);
    cudaGetSymbolAddress((void**)&kv,   g_kv);
    cudaGetSymbolAddress((void**)&wp,   g_wp);
    cudaGetSymbolAddress((void**)&bp,   g_bp);
    cudaGetSymbolAddress((void**)&pm,   g_pm);
    cudaGetSymbolAddress((void**)&pz,   g_pz);
    cudaGetSymbolAddress((void**)&qm,   g_qm);
    cudaGetSymbolAddress((void**)&qz,   g_qz);
    cudaGetSymbolAddress((void**)&km,   g_km);
    cudaGetSymbolAddress((void**)&kz,   g_kz);
    cudaGetSymbolAddress((void**)&bm,   g_bm);
    cudaGetSymbolAddress((void**)&bmp,  g_bmp);
    cudaGetSymbolAddress((void**)&part, g_part);
    cudaGetSymbolAddress((void**)&stat, g_stat);
    cudaGetSymbolAddress((void**)&ah,   g_ah);
    cudaGetSymbolAddress((void**)&al,   g_al);
    cudaGetSymbolAddress((void**)&bh,   g_bh);
    cudaGetSymbolAddress((void**)&bl,   g_bl);
    cudaGetSymbolAddress((void**)&zh,   g_zh);
    cudaGetSymbolAddress((void**)&zl,   g_zl);
    cudaGetSymbolAddress((void**)&hh,   g_hh);
    cudaGetSymbolAddress((void**)&hl,   g_hl);
    cudaGetSymbolAddress((void**)&w1h,  g_w1h);
    cudaGetSymbolAddress((void**)&w1l,  g_w1l);
    cudaGetSymbolAddress((void**)&w2h,  g_w2h);
    cudaGetSymbolAddress((void**)&w2l,  g_w2l);

    // raise dynamic-smem limits (idempotent; not a stream op)
    cudaFuncSetAttribute(mma_gemm<128,128,64,32,0,1,0>,
        cudaFuncAttributeMaxDynamicSharedMemorySize, GSMEM(128,128));
    cudaFuncSetAttribute(mma_gemm<128,128,64,32,0,0,0>,
        cudaFuncAttributeMaxDynamicSharedMemorySize, GSMEM(128,128));
    cudaFuncSetAttribute(mma_gemm<128,128,64,32,1,1,0>,
        cudaFuncAttributeMaxDynamicSharedMemorySize, GSMEM(128,128));
    cudaFuncSetAttribute(mma_gemm<64,64,32,32,1,0,1>,
        cudaFuncAttributeMaxDynamicSharedMemorySize, GSMEM(64,64));

    // ===== LFFN fused-weight prep =====
    tsplit<<<dim3(ST/32, DHI/32), dim3(32,8)>>>(D1, ST, DHI, ah, al);
    mma_gemm<64,64,32,32,1,0,1><<<dim3(DDIM/64, DHI/64), 128, GSMEM(64,64)>>>(
        ah, al, E1, nullptr, ST, nullptr, w1h, w1l, DDIM, nullptr, nullptr, 0);
    tsplit<<<dim3(ST/32, DDIM/32), dim3(32,8)>>>(D2, ST, DDIM, ah, al);
    mma_gemm<64,64,32,32,1,0,1><<<dim3(DHI/64, DDIM/64), 128, GSMEM(64,64)>>>(
        ah, al, E2, nullptr, ST, nullptr, w2h, w2l, DHI, nullptr, nullptr, 0);

    // ===== masked self-attention =====
    pack_qkv<<<(DDIM*384 + 255)/256, 256>>>(Wq_sa, Wk_sa, Wv_sa, bq_sa, bk_sa, bv_sa, wp, bp);
    tsplit<<<dim3(DDIM/32, 384/32), dim3(32,8)>>>(wp, DDIM, 384, bh, bl);
    mma_gemm<128,128,64,32,0,1,0><<<dim3(3, TOK/128), 256, GSMEM(128,128)>>>(
        y_in, nullptr, bh, bl, DDIM, qkv, nullptr, nullptr, 384, bp, nullptr, 0);
    colpart<<<dim3(8, BB), 256>>>(qkv, 384,   0, ST, 1, pm, pz);
    colmerge<<<BB, 128>>>(pm, pz, qm, qz);
    colpart<<<dim3(8, BB), 256>>>(qkv, 384, 128, ST, 0, pm, pz);
    colmerge<<<BB, 128>>>(pm, pz, km, kz);
    bmpart<<<dim3(8, 16), 256>>>(qkv, 384, 128, qkv, 384, 256, ST, km, bmp);
    bm_reduce<<<16*4096/256, 256>>>(bmp, kz, bm);
    z_kernel<<<TOK/16, 256>>>(qkv, 384, bm, qm, qz, zh, zl, 1);
    tsplit<<<dim3(128/32, DDIM/32), dim3(32,8)>>>(Wo_sa, 128, DDIM, bh, bl);
    mma_gemm<128,128,64,32,0,0,0><<<dim3(4, TOK/128), 256, GSMEM(128,128)>>>(
        zh, zl, bh, bl, 128, yp, nullptr, nullptr, DDIM, bo_sa, y_in, 0);
    ln_part<<<dim3(32, BB), 256>>>(yp, part);
    ln_final<<<BB, 32>>>(part, stat);
    ln_apply<<<TOK*DDIM/4/256, 256>>>(yp, g1, b1, stat, yp);

    // ===== cross-attention =====
    pack_qkv<<<(DDIM*384 + 255)/256, 256>>>(Wq_x, Wk_x, Wv_x, bq_x, bk_x, bv_x, wp, bp);
    tsplit<<<dim3(DDIM/32, 384/32), dim3(32,8)>>>(wp, DDIM, 384, bh, bl);
    mma_gemm<128,128,64,32,0,1,0><<<dim3(1, TOK/128), 256, GSMEM(128,128)>>>(
        yp, nullptr, bh, bl, DDIM, qx, nullptr, nullptr, 128, bp, nullptr, 0);
    mma_gemm<128,128,64,32,0,1,0><<<dim3(2, TOKM/128), 256, GSMEM(128,128)>>>(
        mem, nullptr, bh + 128*DDIM, bl + 128*DDIM, DDIM, kv, nullptr, nullptr,
        256, bp + 128, nullptr, 0);
    colpart<<<dim3(8, BB), 256>>>(qx, 128, 0, ST,  0, pm, pz);
    colmerge<<<BB, 128>>>(pm, pz, qm, qz);
    colpart<<<dim3(8, BB), 256>>>(kv, 256, 0, SMM, 0, pm, pz);
    colmerge<<<BB, 128>>>(pm, pz, km, kz);
    bmpart<<<dim3(8, 16), 256>>>(kv, 256, 0, kv, 256, 128, SMM, km, bmp);
    bm_reduce<<<16*4096/256, 256>>>(bmp, kz, bm);
    z_kernel<<<TOK/16, 256>>>(qx, 128, bm, qm, qz, zh, zl, 0);
    tsplit<<<dim3(128/32, DDIM/32), dim3(32,8)>>>(Wo_x, 128, DDIM, bh, bl);
    mma_gemm<128,128,64,32,0,0,0><<<dim3(4, TOK/128), 256, GSMEM(128,128)>>>(
        zh, zl, bh, bl, 128, yp, nullptr, nullptr, DDIM, bo_x, yp, 0);
    ln_part<<<dim3(32, BB), 256>>>(yp, part);
    ln_final<<<BB, 32>>>(part, stat);
    ln_apply<<<TOK*DDIM/4/256, 256>>>(yp, g2, b2, stat, yp);

    // ===== LFFN =====
    mma_gemm<128,128,64,32,1,1,0><<<dim3(DHI/128, TOK/128), 256, GSMEM(128,128)>>>(
        yp, nullptr, w1h, w1l, DDIM, nullptr, hh, hl, DHI, nullptr, nullptr, 1);
    mma_gemm<128,128,64,32,0,0,0><<<dim3(4, TOK/128), 256, GSMEM(128,128)>>>(
        hh, hl, w2h, w2l, DHI, yp, nullptr, nullptr, DDIM, nullptr, yp, 0);
    ln_part<<<dim3(32, BB), 256>>>(yp, part);
    ln_final<<<BB, 32>>>(part, stat);
    ln_apply<<<TOK*DDIM/4/256, 256>>>(yp, g3, b3, stat, out);
}

// round 15
// speedup vs baseline: 1.1387x; 1.1387x over previous
#include <cuda_runtime.h>
#include <cuda_bf16.h>
#include <cstdint>
typedef __nv_bfloat16 bf16;

#define INV_DQ4 0.35355339059327373f
#define BB   8
#define ST   2048
#define SMM  1024
#define DDIM 512
#define DHI  1024
#define TOK  16384
#define TOKM 8192
#define PERB (ST*DDIM)

// ---------------- scratch ----------------
__device__ float g_y[TOK*DDIM];
__device__ float g_qkv[TOK*384];
__device__ float g_qx[TOK*128];
__device__ float g_kv[TOKM*256];
__device__ float g_wp[DDIM*384];
__device__ float g_bp[384];
__device__ float g_pm[BB*8*128], g_pz[BB*8*128];
__device__ float g_qm[BB*128], g_qz[BB*128];
__device__ float g_km[BB*128], g_kz[BB*128];
__device__ float g_bm[16*4096];
__device__ float g_bmp[16*8*4096];
__device__ float g_part[BB*32*2];
__device__ float g_stat[BB*2];
__device__ float g_wk[8*DHI*DDIM];                 // split-K partials (16 MB)
__device__ bf16  g_ah[TOK*DDIM], g_al[TOK*DDIM];   // A-side activations hi/lo
__device__ bf16  g_bh[DHI*ST],   g_bl[DHI*ST];     // B-side weights hi/lo
__device__ bf16  g_zh[TOK*128],  g_zl[TOK*128];
__device__ bf16  g_hh[TOK*DHI],  g_hl[TOK*DHI];
__device__ bf16  g_w1h[DHI*DDIM], g_w1l[DHI*DDIM];
__device__ bf16  g_w2h[DDIM*DHI], g_w2l[DDIM*DHI];

// ---------------- split: fp32 -> bf16 hi/lo ----------------
__global__ void splitf(const float* __restrict__ src, bf16* __restrict__ hi,
                       bf16* __restrict__ lo, int n8)
{
    int i = blockIdx.x * 256 + threadIdx.x;
    if (i >= n8) return;
    float4 a = ((const float4*)src)[(long)i*2];
    float4 b = ((const float4*)src)[(long)i*2 + 1];
    float v[8] = {a.x,a.y,a.z,a.w,b.x,b.y,b.z,b.w};
    bf16 h[8], l[8];
    #pragma unroll
    for (int k = 0; k < 8; k++) {
        h[k] = __float2bfloat16(v[k]);
        l[k] = __float2bfloat16(v[k] - __bfloat162float(h[k]));
    }
    ((uint4*)hi)[i] = *(uint4*)h;
    ((uint4*)lo)[i] = *(uint4*)l;
}

// W[K][N] fp32 -> T[N][K] bf16 hi/lo
__global__ void tsplit(const float* __restrict__ W, int K, int N,
                       bf16* __restrict__ Th, bf16* __restrict__ Tl)
{
    __shared__ float t[32][33];
    int k0 = blockIdx.x * 32, n0 = blockIdx.y * 32;
    for (int i = threadIdx.y; i < 32; i += 8)
        t[i][threadIdx.x] = W[(long)(k0 + i) * N + n0 + threadIdx.x];
    __syncthreads();
    for (int i = threadIdx.y; i < 32; i += 8) {
        float v = t[threadIdx.x][i];
        bf16 h = __float2bfloat16(v);
        long o = (long)(n0 + i) * K + k0 + threadIdx.x;
        Th[o] = h;
        Tl[o] = __float2bfloat16(v - __bfloat162float(h));
    }
}

// sum ns split-K partials -> bf16 hi/lo
__global__ void wreduce(const float* __restrict__ p, long psize, int ns,
                        bf16* __restrict__ oh, bf16* __restrict__ ol, long n)
{
    long i = (long)blockIdx.x * 256 + threadIdx.x;
    if (i >= n) return;
    float s = 0.f;
    for (int c = 0; c < ns; c++) s += p[c*psize + i];
    bf16 h = __float2bfloat16(s);
    oh[i] = h;
    ol[i] = __float2bfloat16(s - __bfloat162float(h));
}

// ---------------- bf16-split tensor-core GEMM (R13 core + ldk/split-K) ----
#define MMA_BF16(d, a, b) asm volatile( \
    "mma.sync.aligned.m16n8k16.row.col.f32.bf16.bf16.f32 " \
    "{%0,%1,%2,%3}, {%4,%5,%6,%7}, {%8,%9}, {%0,%1,%2,%3};" \
    : "+f"(d[0]), "+f"(d[1]), "+f"(d[2]), "+f"(d[3]) \
    : "r"(a[0]), "r"(a[1]), "r"(a[2]), "r"(a[3]), "r"(b[0]), "r"(b[1]))

#define LDSM4(R, a) asm volatile( \
    "ldmatrix.sync.aligned.m8n8.x4.shared.b16 {%0,%1,%2,%3}, [%4];" \
    : "=r"((R)[0]), "=r"((R)[1]), "=r"((R)[2]), "=r"((R)[3]) : "r"(a))

// C[M,N] = (Ah+Al)[M,*] @ (Bh+Bl)[N,*]^T over K columns starting at
// blockIdx.z*K, row stride ldk. OUT==0: fp32 +bias/act/res. OUT==1: bf16
// hi/lo (+act). OUT==2: fp32 split-K partial at C + z*(Mtot*ldc).
template<int BM, int BN, int WM, int WN, int OUT>
__global__ void __launch_bounds__((BM/WM)*(BN/WN)*32) mma_gemm(
    const bf16* __restrict__ Ah, const bf16* __restrict__ Al,
    const bf16* __restrict__ Bh, const bf16* __restrict__ Bl,
    int K, int ldk, float* __restrict__ C, bf16* __restrict__ Ch,
    bf16* __restrict__ Cl, int ldc, const float* __restrict__ bias,
    const float* __restrict__ res, int act)
{
    constexpr int NWN = BN / WN;
    constexpr int NT  = (BM/WM) * NWN * 32;
    constexpr int MT  = WM / 16, NTL = WN / 8;
    __shared__ __align__(128) uint4 sA[BM*8];
    __shared__ __align__(128) uint4 sB[BN*8];
    const int tid = threadIdx.x, wid = tid >> 5, lane = tid & 31;
    const int wm = wid / NWN, wn = wid % NWN;
    const int lr8 = lane & 7, g = lane >> 3;
    const int lq = lane & 3, lr = lane >> 2;
    const long row0 = (long)blockIdx.y * BM;
    const long col0 = (long)blockIdx.x * BN;
    const long kz0  = (long)blockIdx.z * K;
    const uint32_t saA = (uint32_t)__cvta_generic_to_shared(sA);
    const uint32_t saB = (uint32_t)__cvta_generic_to_shared(sB);
    constexpr int ITA = (BM*4) / NT, ITB = (BN*4) / NT;
    uint4 rah[ITA], ral[ITA], rbh[ITB], rbl[ITB];

    auto ldg = [&](int k0) {
        #pragma unroll
        for (int i = 0; i < ITA; i++) {
            int idx = tid + i*NT;
            long off = (row0 + (idx>>2)) * (long)ldk + kz0 + k0 + ((idx&3)<<3);
            rah[i] = *(const uint4*)(Ah + off);
            ral[i] = *(const uint4*)(Al + off);
        }
        #pragma unroll
        for (int i = 0; i < ITB; i++) {
            int idx = tid + i*NT;
            long off = (col0 + (idx>>2)) * (long)ldk + kz0 + k0 + ((idx&3)<<3);
            rbh[i] = *(const uint4*)(Bh + off);
            rbl[i] = *(const uint4*)(Bl + off);
        }
    };
    auto sts = [&]() {
        #pragma unroll
        for (int i = 0; i < ITA; i++) {
            int idx = tid + i*NT;
            int row = idx >> 2, c = idx & 3;
            int w = row*8 + (c ^ (row & 7));
            sA[w] = rah[i]; sA[w ^ 4] = ral[i];
        }
        #pragma unroll
        for (int i = 0; i < ITB; i++) {
            int idx = tid + i*NT;
            int row = idx >> 2, c = idx & 3;
            int w = row*8 + (c ^ (row & 7));
            sB[w] = rbh[i]; sB[w ^ 4] = rbl[i];
        }
    };

    float acc[MT][NTL][4];
    #pragma unroll
    for (int i = 0; i < MT; i++)
        #pragma unroll
        for (int j = 0; j < NTL; j++) {
            acc[i][j][0]=0.f; acc[i][j][1]=0.f; acc[i][j][2]=0.f; acc[i][j][3]=0.f;
        }

    auto compute = [&]() {
        #pragma unroll
        for (int ks = 0; ks < 2; ks++) {
            uint32_t afh[MT][4], afl[MT][4], bfh[NTL][2], bfl[NTL][2];
            #pragma unroll
            for (int i = 0; i < MT; i++) {
                int row = wm*WM + i*16 + ((g & 1) << 3) + lr8;
                int ch  = (ks << 1) + (g >> 1);
                uint32_t ad = saA + row*128 + ((ch ^ lr8) << 4);
                LDSM4(afh[i], ad);
                LDSM4(afl[i], ad ^ 64u);
            }
            #pragma unroll
            for (int jj = 0; jj < NTL/2; jj++) {
                int row = wn*WN + jj*16 + ((g >> 1) << 3) + lr8;
                int ch  = (ks << 1) + (g & 1);
                uint32_t ad = saB + row*128 + ((ch ^ lr8) << 4);
                uint32_t t[4];
                LDSM4(t, ad);
                bfh[2*jj][0]=t[0]; bfh[2*jj][1]=t[1];
                bfh[2*jj+1][0]=t[2]; bfh[2*jj+1][1]=t[3];
                LDSM4(t, ad ^ 64u);
                bfl[2*jj][0]=t[0]; bfl[2*jj][1]=t[1];
                bfl[2*jj+1][0]=t[2]; bfl[2*jj+1][1]=t[3];
            }
            #pragma unroll
            for (int i = 0; i < MT; i++)
                #pragma unroll
                for (int j = 0; j < NTL; j++) {
                    MMA_BF16(acc[i][j], afh[i], bfh[j]);
                    MMA_BF16(acc[i][j], afh[i], bfl[j]);
                    MMA_BF16(acc[i][j], afl[i], bfh[j]);
                }
        }
    };

    ldg(0); sts(); __syncthreads();
    for (int k0 = 32; k0 < K; k0 += 32) {
        ldg(k0);
        compute();
        __syncthreads();
        sts();
        __syncthreads();
    }
    compute();

    float* Cz = C;
    if (OUT == 2) Cz = C + (long)blockIdx.z * ((long)gridDim.y * BM * ldc);

    #pragma unroll
    for (int i = 0; i < MT; i++) {
        int r = (int)row0 + wm*WM + i*16 + lr;
        #pragma unroll
        for (int j = 0; j < NTL; j++) {
            int cb = (int)col0 + wn*WN + j*8 + 2*lq;
            float v[4] = {acc[i][j][0], acc[i][j][1], acc[i][j][2], acc[i][j][3]};
            if (OUT != 2 && bias) { float b0 = bias[cb], b1 = bias[cb+1];
                        v[0]+=b0; v[1]+=b1; v[2]+=b0; v[3]+=b1; }
            if (OUT != 2 && act) {
                #pragma unroll
                for (int q = 0; q < 4; q++) v[q] = v[q] / (1.f + __expf(-v[q]));
            }
            long o0 = (long)r*ldc + cb, o1 = o0 + 8L*ldc;
            if (OUT == 1) {
                long oo[4] = {o0, o0+1, o1, o1+1};
                #pragma unroll
                for (int q = 0; q < 4; q++) {
                    bf16 h = __float2bfloat16(v[q]);
                    Ch[oo[q]] = h;
                    Cl[oo[q]] = __float2bfloat16(v[q] - __bfloat162float(h));
                }
            } else {
                if (OUT == 0 && res) {
                    v[0]+=res[o0]; v[1]+=res[o0+1]; v[2]+=res[o1]; v[3]+=res[o1+1];
                }
                *(float2*)(Cz + o0) = make_float2(v[0], v[1]);
                *(float2*)(Cz + o1) = make_float2(v[2], v[3]);
            }
        }
    }
}

// ---------------- QKV weight packing ----------------
__global__ void pack_qkv(const float* __restrict__ Wq, const float* __restrict__ Wk,
                         const float* __restrict__ Wv, const float* __restrict__ bq,
                         const float* __restrict__ bk, const float* __restrict__ bv,
                         float* __restrict__ wp, float* __restrict__ bp)
{
    int idx = blockIdx.x * blockDim.x + threadIdx.x;
    if (idx < DDIM * 384) {
        int d = idx / 384, j = idx % 384;
        int p = j >> 7, jj = j & 127;
        int h = jj >> 6, e = jj & 63;
        const float* src = (p == 0) ? Wq : (p == 1) ? Wk : Wv;
        wp[idx] = src[((long)h * DDIM + d) * 64 + e];
    }
    if (idx < 384) {
        int p = idx >> 7, jj = idx & 127;
        const float* sb = (p == 0) ? bq : (p == 1) ? bk : bv;
        bp[idx] = sb[jj];
    }
}

// ---------------- coalesced column softmax stats (online) ----------------
__global__ void colpart(const float* __restrict__ X, int ld, int coloff, int S,
                        int mask, float* __restrict__ pm, float* __restrict__ pz)
{
    int chunk = blockIdx.x, b = blockIdx.y;
    int R = S >> 3;
    int rgrp = threadIdx.x >> 5, cg = threadIdx.x & 31;
    const float* base = X + ((long)(b*S + chunk*R + rgrp))*ld + coloff + cg*4;
    float m[4] = {-1e30f,-1e30f,-1e30f,-1e30f}, z[4] = {0.f,0.f,0.f,0.f};
    int e0 = (cg*4) & 63;
    for (int r = 0; r < R; r += 8) {
        float4 vv = *(const float4*)(base + (long)r*ld);
        int s = chunk*R + rgrp + r;
        float va[4] = {vv.x, vv.y, vv.z, vv.w};
        #pragma unroll
        for (int c = 0; c < 4; c++) {
            if (mask && (e0 + c) > s) continue;
            float val = va[c] * INV_DQ4;
            if (val <= m[c]) z[c] += __expf(val - m[c]);
            else { z[c] = z[c]*__expf(m[c] - val) + 1.f; m[c] = val; }
        }
    }
    __shared__ float sm_[8][128], sz_[8][128];
    #pragma unroll
    for (int c = 0; c < 4; c++) { sm_[rgrp][cg*4+c] = m[c]; sz_[rgrp][cg*4+c] = z[c]; }
    __syncthreads();
    if (threadIdx.x < 128) {
        int col = threadIdx.x;
        float M = -1e30f, Z = 0.f;
        #pragma unroll
        for (int l = 0; l < 8; l++) {
            float mi = sm_[l][col], zi = sz_[l][col];
            if (zi == 0.f) continue;
            if (mi <= M) Z += zi * __expf(mi - M);
            else { Z = Z*__expf(M - mi) + zi; M = mi; }
        }
        pm[(b*8 + chunk)*128 + col] = M;
        pz[(b*8 + chunk)*128 + col] = Z;
    }
}

__global__ void colmerge(const float* __restrict__ pm, const float* __restrict__ pz,
                         float* __restrict__ mo, float* __restrict__ zo)
{
    int b = blockIdx.x, col = threadIdx.x;
    float M = -1e30f, Z = 0.f;
    for (int c = 0; c < 8; c++) {
        float mi = pm[(b*8 + c)*128 + col], zi = pz[(b*8 + c)*128 + col];
        if (zi == 0.f) continue;
        if (mi <= M) Z += zi * __expf(mi - M);
        else { Z = Z*__expf(M - mi) + zi; M = mi; }
    }
    mo[b*128 + col] = M;
    zo[b*128 + col] = Z;
}

// ---------------- Bm partials (exp fused into loader) ----------------
__global__ void __launch_bounds__(256) bmpart(
    const float* __restrict__ Kb, int ldk, int koff,
    const float* __restrict__ Vb, int ldv, int voff,
    int S, const float* __restrict__ km, float* __restrict__ bmp)
{
    int chunk = blockIdx.x, blk = blockIdx.y;   // blk = h*8+b
    int h = blk >> 3, b = blk & 7;
    int R = S >> 3;
    int tid = threadIdx.x;
    int e = tid >> 2, d0 = (tid & 3) * 16;
    __shared__ float Ks[64][64];
    __shared__ float Vs[64][64];
    float acc[16];
    #pragma unroll
    for (int i = 0; i < 16; i++) acc[i] = 0.f;
    const float* kp = Kb + (long)(b*S + chunk*R) * ldk + koff + h*64;
    const float* vp = Vb + (long)(b*S + chunk*R) * ldv + voff + h*64;
    const float* kmb = km + b*128 + h*64;
    for (int t = 0; t < R/64; t++) {
        for (int idx = tid; idx < 64*16; idx += 256) {
            int r = idx >> 4, c4 = (idx & 15) << 2;
            float4 kk = *(const float4*)(kp + (long)(t*64 + r)*ldk + c4);
            float4 mm = *(const float4*)(kmb + c4);
            kk.x = __expf(kk.x*INV_DQ4 - mm.x);
            kk.y = __expf(kk.y*INV_DQ4 - mm.y);
            kk.z = __expf(kk.z*INV_DQ4 - mm.z);
            kk.w = __expf(kk.w*INV_DQ4 - mm.w);
            *(float4*)&Ks[r][c4] = kk;
            *(float4*)&Vs[r][c4] = *(const float4*)(vp + (long)(t*64 + r)*ldv + c4);
        }
        __syncthreads();
        #pragma unroll 4
        for (int s = 0; s < 64; s++) {
            float w = Ks[s][e];
            #pragma unroll
            for (int dd = 0; dd < 16; dd++) acc[dd] += w * Vs[s][d0 + dd];
        }
        __syncthreads();
    }
    float* outp = bmp + ((long)blk*8 + chunk)*4096 + e*64 + d0;
    #pragma unroll
    for (int dd = 0; dd < 16; dd++) outp[dd] = acc[dd];
}

__global__ void bm_reduce(const float* __restrict__ bmp, const float* __restrict__ kz,
                          float* __restrict__ bm)
{
    int gid = blockIdx.x * 256 + threadIdx.x;
    int blk = gid >> 12, r = gid & 4095;
    int h = blk >> 3, b = blk & 7, e = r >> 6;
    float s = 0.f;
    for (int c = 0; c < 8; c++) s += bmp[((long)blk*8 + c)*4096 + r];
    bm[(long)blk*4096 + r] = s / kz[b*128 + h*64 + e];
}

// ---------------- Z = A @ Bm (w precomputed; bf16 hi/lo out) ----------------
__global__ void __launch_bounds__(256) z_kernel(
    const float* __restrict__ Q, int ldq, const float* __restrict__ bm,
    const float* __restrict__ qm, const float* __restrict__ qz,
    bf16* __restrict__ Zh, bf16* __restrict__ Zl, int mask)
{
    __shared__ float Bs[2][64][64];
    __shared__ float ws[16][130];
    int tid = threadIdx.x;
    int row0 = blockIdx.x * 16;
    int b = row0 / ST;
    for (int idx = tid; idx < 2048; idx += 256) {
        int hh = idx >> 10, rr = (idx >> 4) & 63, c4 = (idx & 15) << 2;
        *(float4*)&Bs[hh][rr][c4] =
            *(const float4*)(bm + ((long)(hh*BB + b) * 64 + rr) * 64 + c4);
    }
    #pragma unroll
    for (int k = 0; k < 8; k++) {
        int idx = tid + k*256;
        int rid = idx >> 7, je = idx & 127;
        int e = je & 63;
        int s = (row0 + rid) & (ST - 1);
        float w = 0.f;
        if (!(mask && e > s)) {
            float q = Q[(long)(row0 + rid)*ldq + je];
            w = __expf(q*INV_DQ4 - qm[b*128 + je]) / qz[b*128 + je];
        }
        ws[rid][je] = w;
    }
    __syncthreads();
    int rid = tid >> 4, sub = tid & 15;
    int h = sub >> 3, d0 = (sub & 7) * 8;
    float acc[8];
    #pragma unroll
    for (int i = 0; i < 8; i++) acc[i] = 0.f;
    const float* wsr = &ws[rid][h*64];
    for (int e = 0; e < 64; e++) {
        float w = wsr[e];
        const float* bp = &Bs[h][e][d0];
        #pragma unroll
        for (int dd = 0; dd < 8; dd++) acc[dd] += w * bp[dd];
    }
    long o = (long)(row0 + rid) * 128 + h*64 + d0;
    #pragma unroll
    for (int dd = 0; dd < 8; dd++) {
        bf16 hh2 = __float2bfloat16(acc[dd]);
        Zh[o + dd] = hh2;
        Zl[o + dd] = __float2bfloat16(acc[dd] - __bfloat162float(hh2));
    }
}

// ---------------- LayerNorm ----------------
__global__ void ln_part(const float* __restrict__ X, float* __restrict__ part)
{
    int b = blockIdx.y, chunk = blockIdx.x;
    const float4* p = (const float4*)(X + (long)b*PERB) + (long)chunk*8192 + threadIdx.x;
    float s = 0.f, q = 0.f;
    for (int k = 0; k < 32; k++) {
        float4 v = p[(long)k*256];
        s += v.x + v.y + v.z + v.w;
        q += v.x*v.x + v.y*v.y + v.z*v.z + v.w*v.w;
    }
    __shared__ float rs[256], rq[256];
    rs[threadIdx.x] = s; rq[threadIdx.x] = q; __syncthreads();
    for (int st = 128; st > 0; st >>= 1) {
        if (threadIdx.x < st) {
            rs[threadIdx.x] += rs[threadIdx.x + st];
            rq[threadIdx.x] += rq[threadIdx.x + st];
        }
        __syncthreads();
    }
    if (threadIdx.x == 0) {
        part[(b*32 + chunk)*2]     = rs[0];
        part[(b*32 + chunk)*2 + 1] = rq[0];
    }
}

__global__ void ln_final(const float* __restrict__ part, float* __restrict__ stat)
{
    int b = blockIdx.x;
    float s = part[(b*32 + threadIdx.x)*2];
    float q = part[(b*32 + threadIdx.x)*2 + 1];
    for (int o = 16; o > 0; o >>= 1) {
        s += __shfl_down_sync(0xffffffffu, s, o);
        q += __shfl_down_sync(0xffffffffu, q, o);
    }
    if (threadIdx.x == 0) {
        float mean = s / (float)PERB;
        float var  = q / (float)PERB - mean * mean;
        stat[b*2] = mean; stat[b*2 + 1] = rsqrtf(var + 1e-5f);
    }
}

// out fp32 (+ optional bf16 hi/lo split emit)
__global__ void ln_apply(const float* __restrict__ X, const float* __restrict__ g,
                         const float* __restrict__ bt, const float* __restrict__ stat,
                         float* __restrict__ out, bf16* __restrict__ oh,
                         bf16* __restrict__ ol)
{
    long i4  = (long)blockIdx.x * blockDim.x + threadIdx.x;
    long idx = i4 * 4;
    int  b   = (int)(idx / PERB);
    long gi  = idx % PERB;
    float mean = stat[b*2], rstd = stat[b*2 + 1];
    float4 x  = *(const float4*)(X + idx);
    float4 gg = *(const float4*)(g + gi);
    float4 bb = *(const float4*)(bt + gi);
    float4 o;
    o.x = (x.x - mean) * rstd * gg.x + bb.x;
    o.y = (x.y - mean) * rstd * gg.y + bb.y;
    o.z = (x.z - mean) * rstd * gg.z + bb.z;
    o.w = (x.w - mean) * rstd * gg.w + bb.w;
    *(float4*)(out + idx) = o;
    if (oh) {
        float v[4] = {o.x, o.y, o.z, o.w};
        bf16 h[4], l[4];
        #pragma unroll
        for (int k = 0; k < 4; k++) {
            h[k] = __float2bfloat16(v[k]);
            l[k] = __float2bfloat16(v[k] - __bfloat162float(h[k]));
        }
        ((uint2*)oh)[i4] = *(uint2*)h;
        ((uint2*)ol)[i4] = *(uint2*)l;
    }
}

// ---------------- host orchestration ----------------
extern "C" void kernel_launch(void* const* d_in, const int* in_sizes, int n_in,
                              void* d_out, int out_size)
{
    (void)in_sizes; (void)n_in; (void)out_size;
    const float* mem   = (const float*)d_in[0];
    const float* y_in  = (const float*)d_in[1];
    const float* Wq_sa = (const float*)d_in[2];
    const float* bq_sa = (const float*)d_in[3];
    const float* Wk_sa = (const float*)d_in[4];
    const float* bk_sa = (const float*)d_in[5];
    const float* Wv_sa = (const float*)d_in[6];
    const float* bv_sa = (const float*)d_in[7];
    const float* Wo_sa = (const float*)d_in[8];
    const float* bo_sa = (const float*)d_in[9];
    const float* Wq_x  = (const float*)d_in[10];
    const float* bq_x  = (const float*)d_in[11];
    const float* Wk_x  = (const float*)d_in[12];
    const float* bk_x  = (const float*)d_in[13];
    const float* Wv_x  = (const float*)d_in[14];
    const float* bv_x  = (const float*)d_in[15];
    const float* Wo_x  = (const float*)d_in[16];
    const float* bo_x  = (const float*)d_in[17];
    const float* E1    = (const float*)d_in[18];
    const float* D1    = (const float*)d_in[19];
    const float* E2    = (const float*)d_in[20];
    const float* D2    = (const float*)d_in[21];
    const float* g1    = (const float*)d_in[22];
    const float* b1    = (const float*)d_in[23];
    const float* g2    = (const float*)d_in[24];
    const float* b2    = (const float*)d_in[25];
    const float* g3    = (const float*)d_in[26];
    const float* b3    = (const float*)d_in[27];
    float* out = (float*)d_out;

    float *yp,*qkv,*qx,*kv,*wp,*bp,*pm,*pz,*qm,*qz,*km,*kz,*bm,*bmp,*part,*stat,*wk;
    bf16 *ah,*al,*bh,*bl,*zh,*zl,*hh,*hl,*w1h,*w1l,*w2h,*w2l;
    cudaGetSymbolAddress((void**)&yp,   g_y);
    cudaGetSymbolAddress((void**)&qkv,  g_qkv);
    cudaGetSymbolAddress((void**)&qx,   g_qx);
    cudaGetSymbolAddress((void**)&kv,   g_kv);
    cudaGetSymbolAddress((void**)&wp,   g_wp);
    cudaGetSymbolAddress((void**)&bp,   g_bp);
    cudaGetSymbolAddress((void**)&pm,   g_pm);
    cudaGetSymbolAddress((void**)&pz,   g_pz);
    cudaGetSymbolAddress((void**)&qm,   g_qm);
    cudaGetSymbolAddress((void**)&qz,   g_qz);
    cudaGetSymbolAddress((void**)&km,   g_km);
    cudaGetSymbolAddress((void**)&kz,   g_kz);
    cudaGetSymbolAddress((void**)&bm,   g_bm);
    cudaGetSymbolAddress((void**)&bmp,  g_bmp);
    cudaGetSymbolAddress((void**)&part, g_part);
    cudaGetSymbolAddress((void**)&stat, g_stat);
    cudaGetSymbolAddress((void**)&wk,   g_wk);
    cudaGetSymbolAddress((void**)&ah,   g_ah);
    cudaGetSymbolAddress((void**)&al,   g_al);
    cudaGetSymbolAddress((void**)&bh,   g_bh);
    cudaGetSymbolAddress((void**)&bl,   g_bl);
    cudaGetSymbolAddress((void**)&zh,   g_zh);
    cudaGetSymbolAddress((void**)&zl,   g_zl);
    cudaGetSymbolAddress((void**)&hh,   g_hh);
    cudaGetSymbolAddress((void**)&hl,   g_hl);
    cudaGetSymbolAddress((void**)&w1h,  g_w1h);
    cudaGetSymbolAddress((void**)&w1l,  g_w1l);
    cudaGetSymbolAddress((void**)&w2h,  g_w2h);
    cudaGetSymbolAddress((void**)&w2l,  g_w2l);

    // ===== LFFN fused-weight prep (split-K over K=2048, 8 chunks) =====
    // W1^T[DHI][DDIM] = D1^T @ E1
    tsplit<<<dim3(ST/32, DHI/32), dim3(32,8)>>>(D1, ST, DHI, ah, al);
    splitf<<<DDIM*ST/8/256, 256>>>(E1, bh, bl, DDIM*ST/8);
    mma_gemm<64,64,32,32,2><<<dim3(DDIM/64, DHI/64, 8), 128>>>(
        ah, al, bh, bl, ST/8, ST, wk, nullptr, nullptr, DDIM, nullptr, nullptr, 0);
    wreduce<<<(DHI*DDIM + 255)/256, 256>>>(wk, (long)DHI*DDIM, 8, w1h, w1l, (long)DHI*DDIM);
    // W2^T[DDIM][DHI] = D2^T @ E2
    tsplit<<<dim3(ST/32, DDIM/32), dim3(32,8)>>>(D2, ST, DDIM, ah, al);
    splitf<<<DHI*ST/8/256, 256>>>(E2, bh, bl, DHI*ST/8);
    mma_gemm<64,64,32,32,2><<<dim3(DHI/64, DDIM/64, 8), 128>>>(
        ah, al, bh, bl, ST/8, ST, wk, nullptr, nullptr, DHI, nullptr, nullptr, 0);
    wreduce<<<(DDIM*DHI + 255)/256, 256>>>(wk, (long)DDIM*DHI, 8, w2h, w2l, (long)DDIM*DHI);

    // ===== masked self-attention =====
    pack_qkv<<<(DDIM*384 + 255)/256, 256>>>(Wq_sa, Wk_sa, Wv_sa, bq_sa, bk_sa, bv_sa, wp, bp);
    tsplit<<<dim3(DDIM/32, 384/32), dim3(32,8)>>>(wp, DDIM, 384, bh, bl);
    splitf<<<TOK*DDIM/8/256, 256>>>(y_in, ah, al, TOK*DDIM/8);
    mma_gemm<128,128,64,32,0><<<dim3(3, TOK/128), 256>>>(
        ah, al, bh, bl, DDIM, DDIM, qkv, nullptr, nullptr, 384, bp, nullptr, 0);
    colpart<<<dim3(8, BB), 256>>>(qkv, 384,   0, ST, 1, pm, pz);
    colmerge<<<BB, 128>>>(pm, pz, qm, qz);
    colpart<<<dim3(8, BB), 256>>>(qkv, 384, 128, ST, 0, pm, pz);
    colmerge<<<BB, 128>>>(pm, pz, km, kz);
    bmpart<<<dim3(8, 16), 256>>>(qkv, 384, 128, qkv, 384, 256, ST, km, bmp);
    bm_reduce<<<16*4096/256, 256>>>(bmp, kz, bm);
    z_kernel<<<TOK/16, 256>>>(qkv, 384, bm, qm, qz, zh, zl, 1);
    tsplit<<<dim3(128/32, DDIM/32), dim3(32,8)>>>(Wo_sa, 128, DDIM, bh, bl);
    mma_gemm<128,128,64,32,0><<<dim3(4, TOK/128), 256>>>(
        zh, zl, bh, bl, 128, 128, yp, nullptr, nullptr, DDIM, bo_sa, y_in, 0);
    ln_part<<<dim3(32, BB), 256>>>(yp, part);
    ln_final<<<BB, 32>>>(part, stat);
    ln_apply<<<TOK*DDIM/4/256, 256>>>(yp, g1, b1, stat, yp, ah, al);

    // ===== cross-attention =====
    pack_qkv<<<(DDIM*384 + 255)/256, 256>>>(Wq_x, Wk_x, Wv_x, bq_x, bk_x, bv_x, wp, bp);
    tsplit<<<dim3(DDIM/32, 384/32), dim3(32,8)>>>(wp, DDIM, 384, bh, bl);
    mma_gemm<128,128,64,32,0><<<dim3(1, TOK/128), 256>>>(
        ah, al, bh, bl, DDIM, DDIM, qx, nullptr, nullptr, 128, bp, nullptr, 0);   // Q
    splitf<<<TOKM*DDIM/8/256, 256>>>(mem, ah, al, TOKM*DDIM/8);
    mma_gemm<128,128,64,32,0><<<dim3(2, TOKM/128), 256>>>(
        ah, al, bh + 128*DDIM, bl + 128*DDIM, DDIM, DDIM, kv, nullptr, nullptr,
        256, bp + 128, nullptr, 0);                                               // K,V
    colpart<<<dim3(8, BB), 256>>>(qx, 128, 0, ST,  0, pm, pz);
    colmerge<<<BB, 128>>>(pm, pz, qm, qz);
    colpart<<<dim3(8, BB), 256>>>(kv, 256, 0, SMM, 0, pm, pz);
    colmerge<<<BB, 128>>>(pm, pz, km, kz);
    bmpart<<<dim3(8, 16), 256>>>(kv, 256, 0, kv, 256, 128, SMM, km, bmp);
    bm_reduce<<<16*4096/256, 256>>>(bmp, kz, bm);
    z_kernel<<<TOK/16, 256>>>(qx, 128, bm, qm, qz, zh, zl, 0);
    tsplit<<<dim3(128/32, DDIM/32), dim3(32,8)>>>(Wo_x, 128, DDIM, bh, bl);
    mma_gemm<128,128,64,32,0><<<dim3(4, TOK/128), 256>>>(
        zh, zl, bh, bl, 128, 128, yp, nullptr, nullptr, DDIM, bo_x, yp, 0);
    ln_part<<<dim3(32, BB), 256>>>(yp, part);
    ln_final<<<BB, 32>>>(part, stat);
    ln_apply<<<TOK*DDIM/4/256, 256>>>(yp, g2, b2, stat, yp, ah, al);

    // ===== LFFN =====
    mma_gemm<128,128,64,32,1><<<dim3(DHI/128, TOK/128), 256>>>(
        ah, al, w1h, w1l, DDIM, DDIM, nullptr, hh, hl, DHI, nullptr, nullptr, 1); // swish
    mma_gemm<128,128,64,32,0><<<dim3(4, TOK/128), 256>>>(
        hh, hl, w2h, w2l, DHI, DHI, yp, nullptr, nullptr, DDIM, nullptr, yp, 0);
    ln_part<<<dim3(32, BB), 256>>>(yp, part);
    ln_final<<<BB, 32>>>(part, stat);
    ln_apply<<<TOK*DDIM/4/256, 256>>>(yp, g3, b3, stat, out, nullptr, nullptr);
}

// round 16
// speedup vs baseline: 1.2607x; 1.1071x over previous
#include <cuda_runtime.h>
#include <cuda_bf16.h>
#include <cstdint>
typedef __nv_bfloat16 bf16;

#define INV_DQ4 0.35355339059327373f
#define BB   8
#define ST   2048
#define SMM  1024
#define DDIM 512
#define DHI  1024
#define TOK  16384
#define TOKM 8192
#define PERB (ST*DDIM)

// ---------------- scratch ----------------
__device__ float g_y[TOK*DDIM];
__device__ float g_qkv[TOK*384];
__device__ float g_qx[TOK*128];
__device__ float g_kv[TOKM*256];
__device__ float g_wp[DDIM*384];
__device__ float g_bp[384];
__device__ float g_pm[BB*8*128], g_pz[BB*8*128];
__device__ float g_qm[BB*128], g_qz[BB*128];
__device__ float g_km[BB*128], g_kz[BB*128];
__device__ float g_bm[16*4096];
__device__ float g_bmp[16*8*4096];
__device__ float g_part[BB*32*2];
__device__ float g_stat[BB*2];
__device__ float g_wk[8*DHI*DDIM];
__device__ bf16  g_ah[TOK*DDIM], g_al[TOK*DDIM];
__device__ bf16  g_bh[DHI*ST],   g_bl[DHI*ST];
__device__ bf16  g_zh[TOK*128],  g_zl[TOK*128];
__device__ bf16  g_hh[TOK*DHI],  g_hl[TOK*DHI];
__device__ bf16  g_w1h[DHI*DDIM], g_w1l[DHI*DDIM];
__device__ bf16  g_w2h[DDIM*DHI], g_w2l[DDIM*DHI];

// ---------------- split: fp32 -> bf16 hi/lo ----------------
__global__ void splitf(const float* __restrict__ src, bf16* __restrict__ hi,
                       bf16* __restrict__ lo, int n8)
{
    int i = blockIdx.x * 256 + threadIdx.x;
    if (i >= n8) return;
    float4 a = ((const float4*)src)[(long)i*2];
    float4 b = ((const float4*)src)[(long)i*2 + 1];
    float v[8] = {a.x,a.y,a.z,a.w,b.x,b.y,b.z,b.w};
    bf16 h[8], l[8];
    #pragma unroll
    for (int k = 0; k < 8; k++) {
        h[k] = __float2bfloat16(v[k]);
        l[k] = __float2bfloat16(v[k] - __bfloat162float(h[k]));
    }
    ((uint4*)hi)[i] = *(uint4*)h;
    ((uint4*)lo)[i] = *(uint4*)l;
}

// W[K][N] fp32 -> T[N][K] bf16 hi/lo
__global__ void tsplit(const float* __restrict__ W, int K, int N,
                       bf16* __restrict__ Th, bf16* __restrict__ Tl)
{
    __shared__ float t[32][33];
    int k0 = blockIdx.x * 32, n0 = blockIdx.y * 32;
    for (int i = threadIdx.y; i < 32; i += 8)
        t[i][threadIdx.x] = W[(long)(k0 + i) * N + n0 + threadIdx.x];
    __syncthreads();
    for (int i = threadIdx.y; i < 32; i += 8) {
        float v = t[threadIdx.x][i];
        bf16 h = __float2bfloat16(v);
        long o = (long)(n0 + i) * K + k0 + threadIdx.x;
        Th[o] = h;
        Tl[o] = __float2bfloat16(v - __bfloat162float(h));
    }
}

// sum ns split-K partials -> bf16 hi/lo
__global__ void wreduce(const float* __restrict__ p, long psize, int ns,
                        bf16* __restrict__ oh, bf16* __restrict__ ol, long n)
{
    long i = (long)blockIdx.x * 256 + threadIdx.x;
    if (i >= n) return;
    float s = 0.f;
    for (int c = 0; c < ns; c++) s += p[c*psize + i];
    bf16 h = __float2bfloat16(s);
    oh[i] = h;
    ol[i] = __float2bfloat16(s - __bfloat162float(h));
}

// ---------------- bf16-split tensor-core GEMM (cp.async 2-stage) ----------
#define MMA_BF16(d, a, b) asm volatile( \
    "mma.sync.aligned.m16n8k16.row.col.f32.bf16.bf16.f32 " \
    "{%0,%1,%2,%3}, {%4,%5,%6,%7}, {%8,%9}, {%0,%1,%2,%3};" \
    : "+f"(d[0]), "+f"(d[1]), "+f"(d[2]), "+f"(d[3]) \
    : "r"(a[0]), "r"(a[1]), "r"(a[2]), "r"(a[3]), "r"(b[0]), "r"(b[1]))

#define LDSM4(R, a) asm volatile( \
    "ldmatrix.sync.aligned.m8n8.x4.shared.b16 {%0,%1,%2,%3}, [%4];" \
    : "=r"((R)[0]), "=r"((R)[1]), "=r"((R)[2]), "=r"((R)[3]) : "r"(a))

#define CP16(sa, gp) asm volatile( \
    "cp.async.cg.shared.global [%0], [%1], 16;" :: "r"(sa), "l"(gp))
#define CP_COMMIT  asm volatile("cp.async.commit_group;" ::: "memory")
#define CP_WAIT1   asm volatile("cp.async.wait_group 1;" ::: "memory")
#define CP_WAIT0   asm volatile("cp.async.wait_group 0;" ::: "memory")

// C[M,N] = (Ah+Al)[M,*] @ (Bh+Bl)[N,*]^T over K cols from blockIdx.z*K,
// row stride ldk. OUT==0: fp32 +bias/act/res. OUT==1: bf16 hi/lo (+act).
// OUT==2: fp32 split-K partial. Dynamic smem = 2*(BM+BN)*128 bytes.
template<int BM, int BN, int WM, int WN, int OUT>
__global__ void __launch_bounds__((BM/WM)*(BN/WN)*32, 2) mma_gemm(
    const bf16* __restrict__ Ah, const bf16* __restrict__ Al,
    const bf16* __restrict__ Bh, const bf16* __restrict__ Bl,
    int K, int ldk, float* __restrict__ C, bf16* __restrict__ Ch,
    bf16* __restrict__ Cl, int ldc, const float* __restrict__ bias,
    const float* __restrict__ res, int act)
{
    constexpr int NWN = BN / WN;
    constexpr int NT  = (BM/WM) * NWN * 32;
    constexpr int MT  = WM / 16, NTL = WN / 8;
    extern __shared__ __align__(128) uint4 smem[];
    uint4* sA = smem;                 // 2 stages * BM*8
    uint4* sB = smem + 2*BM*8;        // 2 stages * BN*8
    const int tid = threadIdx.x, wid = tid >> 5, lane = tid & 31;
    const int wm = wid / NWN, wn = wid % NWN;
    const int lr8 = lane & 7, g = lane >> 3;
    const int lq = lane & 3, lr = lane >> 2;
    const long row0 = (long)blockIdx.y * BM;
    const long col0 = (long)blockIdx.x * BN;
    const long kz0  = (long)blockIdx.z * K;
    const uint32_t saA0 = (uint32_t)__cvta_generic_to_shared(sA);
    const uint32_t saB0 = (uint32_t)__cvta_generic_to_shared(sB);
    constexpr int ITA = (BM*4) / NT, ITB = (BN*4) / NT;

    auto cpa = [&](int k0, int st) {
        #pragma unroll
        for (int i = 0; i < ITA; i++) {
            int idx = tid + i*NT;
            int row = idx >> 2, c = idx & 3;
            long off = (row0 + row) * (long)ldk + kz0 + k0 + (c << 3);
            uint32_t sw = (uint32_t)(st*BM*8 + row*8 + (c ^ (row & 7)));
            CP16(saA0 + sw*16, Ah + off);
            CP16(saA0 + (sw ^ 4)*16, Al + off);
        }
        #pragma unroll
        for (int i = 0; i < ITB; i++) {
            int idx = tid + i*NT;
            int row = idx >> 2, c = idx & 3;
            long off = (col0 + row) * (long)ldk + kz0 + k0 + (c << 3);
            uint32_t sw = (uint32_t)(st*BN*8 + row*8 + (c ^ (row & 7)));
            CP16(saB0 + sw*16, Bh + off);
            CP16(saB0 + (sw ^ 4)*16, Bl + off);
        }
    };

    float acc[MT][NTL][4];
    #pragma unroll
    for (int i = 0; i < MT; i++)
        #pragma unroll
        for (int j = 0; j < NTL; j++) {
            acc[i][j][0]=0.f; acc[i][j][1]=0.f; acc[i][j][2]=0.f; acc[i][j][3]=0.f;
        }

    auto compute = [&](int st) {
        uint32_t saA = saA0 + (uint32_t)st*BM*128;
        uint32_t saB = saB0 + (uint32_t)st*BN*128;
        #pragma unroll
        for (int ks = 0; ks < 2; ks++) {
            uint32_t afh[MT][4], afl[MT][4], bfh[NTL][2], bfl[NTL][2];
            #pragma unroll
            for (int i = 0; i < MT; i++) {
                int row = wm*WM + i*16 + ((g & 1) << 3) + lr8;
                int ch  = (ks << 1) + (g >> 1);
                uint32_t ad = saA + row*128 + ((ch ^ lr8) << 4);
                LDSM4(afh[i], ad);
                LDSM4(afl[i], ad ^ 64u);
            }
            #pragma unroll
            for (int jj = 0; jj < NTL/2; jj++) {
                int row = wn*WN + jj*16 + ((g >> 1) << 3) + lr8;
                int ch  = (ks << 1) + (g & 1);
                uint32_t ad = saB + row*128 + ((ch ^ lr8) << 4);
                uint32_t t[4];
                LDSM4(t, ad);
                bfh[2*jj][0]=t[0]; bfh[2*jj][1]=t[1];
                bfh[2*jj+1][0]=t[2]; bfh[2*jj+1][1]=t[3];
                LDSM4(t, ad ^ 64u);
                bfl[2*jj][0]=t[0]; bfl[2*jj][1]=t[1];
                bfl[2*jj+1][0]=t[2]; bfl[2*jj+1][1]=t[3];
            }
            #pragma unroll
            for (int i = 0; i < MT; i++)
                #pragma unroll
                for (int j = 0; j < NTL; j++) {
                    MMA_BF16(acc[i][j], afh[i], bfh[j]);
                    MMA_BF16(acc[i][j], afh[i], bfl[j]);
                    MMA_BF16(acc[i][j], afl[i], bfh[j]);
                }
        }
    };

    const int nt = K >> 5;
    cpa(0, 0); CP_COMMIT;
    for (int t = 0; t < nt; t++) {
        if (t + 1 < nt) { cpa((t+1) << 5, (t+1) & 1); CP_COMMIT; CP_WAIT1; }
        else            { CP_WAIT0; }
        __syncthreads();
        compute(t & 1);
        __syncthreads();
    }

    float* Cz = C;
    if (OUT == 2) Cz = C + (long)blockIdx.z * ((long)gridDim.y * BM * ldc);

    #pragma unroll
    for (int i = 0; i < MT; i++) {
        int r = (int)row0 + wm*WM + i*16 + lr;
        #pragma unroll
        for (int j = 0; j < NTL; j++) {
            int cb = (int)col0 + wn*WN + j*8 + 2*lq;
            float v[4] = {acc[i][j][0], acc[i][j][1], acc[i][j][2], acc[i][j][3]};
            if (OUT != 2 && bias) { float b0 = bias[cb], b1 = bias[cb+1];
                        v[0]+=b0; v[1]+=b1; v[2]+=b0; v[3]+=b1; }
            if (OUT != 2 && act) {
                #pragma unroll
                for (int q = 0; q < 4; q++) v[q] = v[q] / (1.f + __expf(-v[q]));
            }
            long o0 = (long)r*ldc + cb, o1 = o0 + 8L*ldc;
            if (OUT == 1) {
                long oo[4] = {o0, o0+1, o1, o1+1};
                #pragma unroll
                for (int q = 0; q < 4; q++) {
                    bf16 h = __float2bfloat16(v[q]);
                    Ch[oo[q]] = h;
                    Cl[oo[q]] = __float2bfloat16(v[q] - __bfloat162float(h));
                }
            } else {
                if (OUT == 0 && res) {
                    v[0]+=res[o0]; v[1]+=res[o0+1]; v[2]+=res[o1]; v[3]+=res[o1+1];
                }
                *(float2*)(Cz + o0) = make_float2(v[0], v[1]);
                *(float2*)(Cz + o1) = make_float2(v[2], v[3]);
            }
        }
    }
}

// ---------------- QKV weight packing ----------------
__global__ void pack_qkv(const float* __restrict__ Wq, const float* __restrict__ Wk,
                         const float* __restrict__ Wv, const float* __restrict__ bq,
                         const float* __restrict__ bk, const float* __restrict__ bv,
                         float* __restrict__ wp, float* __restrict__ bp)
{
    int idx = blockIdx.x * blockDim.x + threadIdx.x;
    if (idx < DDIM * 384) {
        int d = idx / 384, j = idx % 384;
        int p = j >> 7, jj = j & 127;
        int h = jj >> 6, e = jj & 63;
        const float* src = (p == 0) ? Wq : (p == 1) ? Wk : Wv;
        wp[idx] = src[((long)h * DDIM + d) * 64 + e];
    }
    if (idx < 384) {
        int p = idx >> 7, jj = idx & 127;
        const float* sb = (p == 0) ? bq : (p == 1) ? bk : bv;
        bp[idx] = sb[jj];
    }
}

// ---------------- coalesced column softmax stats (online) ----------------
__global__ void colpart(const float* __restrict__ X, int ld, int coloff, int S,
                        int mask, float* __restrict__ pm, float* __restrict__ pz)
{
    int chunk = blockIdx.x, b = blockIdx.y;
    int R = S >> 3;
    int rgrp = threadIdx.x >> 5, cg = threadIdx.x & 31;
    const float* base = X + ((long)(b*S + chunk*R + rgrp))*ld + coloff + cg*4;
    float m[4] = {-1e30f,-1e30f,-1e30f,-1e30f}, z[4] = {0.f,0.f,0.f,0.f};
    int e0 = (cg*4) & 63;
    for (int r = 0; r < R; r += 8) {
        float4 vv = *(const float4*)(base + (long)r*ld);
        int s = chunk*R + rgrp + r;
        float va[4] = {vv.x, vv.y, vv.z, vv.w};
        #pragma unroll
        for (int c = 0; c < 4; c++) {
            if (mask && (e0 + c) > s) continue;
            float val = va[c] * INV_DQ4;
            if (val <= m[c]) z[c] += __expf(val - m[c]);
            else { z[c] = z[c]*__expf(m[c] - val) + 1.f; m[c] = val; }
        }
    }
    __shared__ float sm_[8][128], sz_[8][128];
    #pragma unroll
    for (int c = 0; c < 4; c++) { sm_[rgrp][cg*4+c] = m[c]; sz_[rgrp][cg*4+c] = z[c]; }
    __syncthreads();
    if (threadIdx.x < 128) {
        int col = threadIdx.x;
        float M = -1e30f, Z = 0.f;
        #pragma unroll
        for (int l = 0; l < 8; l++) {
            float mi = sm_[l][col], zi = sz_[l][col];
            if (zi == 0.f) continue;
            if (mi <= M) Z += zi * __expf(mi - M);
            else { Z = Z*__expf(M - mi) + zi; M = mi; }
        }
        pm[(b*8 + chunk)*128 + col] = M;
        pz[(b*8 + chunk)*128 + col] = Z;
    }
}

__global__ void colmerge(const float* __restrict__ pm, const float* __restrict__ pz,
                         float* __restrict__ mo, float* __restrict__ zo)
{
    int b = blockIdx.x, col = threadIdx.x;
    float M = -1e30f, Z = 0.f;
    for (int c = 0; c < 8; c++) {
        float mi = pm[(b*8 + c)*128 + col], zi = pz[(b*8 + c)*128 + col];
        if (zi == 0.f) continue;
        if (mi <= M) Z += zi * __expf(mi - M);
        else { Z = Z*__expf(M - mi) + zi; M = mi; }
    }
    mo[b*128 + col] = M;
    zo[b*128 + col] = Z;
}

// ---------------- Bm partials (exp fused into loader) ----------------
__global__ void __launch_bounds__(256) bmpart(
    const float* __restrict__ Kb, int ldk, int koff,
    const float* __restrict__ Vb, int ldv, int voff,
    int S, const float* __restrict__ km, float* __restrict__ bmp)
{
    int chunk = blockIdx.x, blk = blockIdx.y;
    int h = blk >> 3, b = blk & 7;
    int R = S >> 3;
    int tid = threadIdx.x;
    int e = tid >> 2, d0 = (tid & 3) * 16;
    __shared__ float Ks[64][64];
    __shared__ float Vs[64][64];
    float acc[16];
    #pragma unroll
    for (int i = 0; i < 16; i++) acc[i] = 0.f;
    const float* kp = Kb + (long)(b*S + chunk*R) * ldk + koff + h*64;
    const float* vp = Vb + (long)(b*S + chunk*R) * ldv + voff + h*64;
    const float* kmb = km + b*128 + h*64;
    for (int t = 0; t < R/64; t++) {
        for (int idx = tid; idx < 64*16; idx += 256) {
            int r = idx >> 4, c4 = (idx & 15) << 2;
            float4 kk = *(const float4*)(kp + (long)(t*64 + r)*ldk + c4);
            float4 mm = *(const float4*)(kmb + c4);
            kk.x = __expf(kk.x*INV_DQ4 - mm.x);
            kk.y = __expf(kk.y*INV_DQ4 - mm.y);
            kk.z = __expf(kk.z*INV_DQ4 - mm.z);
            kk.w = __expf(kk.w*INV_DQ4 - mm.w);
            *(float4*)&Ks[r][c4] = kk;
            *(float4*)&Vs[r][c4] = *(const float4*)(vp + (long)(t*64 + r)*ldv + c4);
        }
        __syncthreads();
        #pragma unroll 4
        for (int s = 0; s < 64; s++) {
            float w = Ks[s][e];
            #pragma unroll
            for (int dd = 0; dd < 16; dd++) acc[dd] += w * Vs[s][d0 + dd];
        }
        __syncthreads();
    }
    float* outp = bmp + ((long)blk*8 + chunk)*4096 + e*64 + d0;
    #pragma unroll
    for (int dd = 0; dd < 16; dd++) outp[dd] = acc[dd];
}

__global__ void bm_reduce(const float* __restrict__ bmp, const float* __restrict__ kz,
                          float* __restrict__ bm)
{
    int gid = blockIdx.x * 256 + threadIdx.x;
    int blk = gid >> 12, r = gid & 4095;
    int h = blk >> 3, b = blk & 7, e = r >> 6;
    float s = 0.f;
    for (int c = 0; c < 8; c++) s += bmp[((long)blk*8 + c)*4096 + r];
    bm[(long)blk*4096 + r] = s / kz[b*128 + h*64 + e];
}

// ---------------- Z = A @ Bm (w precomputed; bf16 hi/lo out) ----------------
__global__ void __launch_bounds__(256) z_kernel(
    const float* __restrict__ Q, int ldq, const float* __restrict__ bm,
    const float* __restrict__ qm, const float* __restrict__ qz,
    bf16* __restrict__ Zh, bf16* __restrict__ Zl, int mask)
{
    __shared__ float Bs[2][64][64];
    __shared__ float ws[16][130];
    int tid = threadIdx.x;
    int row0 = blockIdx.x * 16;
    int b = row0 / ST;
    for (int idx = tid; idx < 2048; idx += 256) {
        int hh = idx >> 10, rr = (idx >> 4) & 63, c4 = (idx & 15) << 2;
        *(float4*)&Bs[hh][rr][c4] =
            *(const float4*)(bm + ((long)(hh*BB + b) * 64 + rr) * 64 + c4);
    }
    #pragma unroll
    for (int k = 0; k < 8; k++) {
        int idx = tid + k*256;
        int rid = idx >> 7, je = idx & 127;
        int e = je & 63;
        int s = (row0 + rid) & (ST - 1);
        float w = 0.f;
        if (!(mask && e > s)) {
            float q = Q[(long)(row0 + rid)*ldq + je];
            w = __expf(q*INV_DQ4 - qm[b*128 + je]) / qz[b*128 + je];
        }
        ws[rid][je] = w;
    }
    __syncthreads();
    int rid = tid >> 4, sub = tid & 15;
    int h = sub >> 3, d0 = (sub & 7) * 8;
    float acc[8];
    #pragma unroll
    for (int i = 0; i < 8; i++) acc[i] = 0.f;
    const float* wsr = &ws[rid][h*64];
    for (int e = 0; e < 64; e++) {
        float w = wsr[e];
        const float* bp = &Bs[h][e][d0];
        #pragma unroll
        for (int dd = 0; dd < 8; dd++) acc[dd] += w * bp[dd];
    }
    long o = (long)(row0 + rid) * 128 + h*64 + d0;
    #pragma unroll
    for (int dd = 0; dd < 8; dd++) {
        bf16 hh2 = __float2bfloat16(acc[dd]);
        Zh[o + dd] = hh2;
        Zl[o + dd] = __float2bfloat16(acc[dd] - __bfloat162float(hh2));
    }
}

// ---------------- LayerNorm ----------------
__global__ void ln_part(const float* __restrict__ X, float* __restrict__ part)
{
    int b = blockIdx.y, chunk = blockIdx.x;
    const float4* p = (const float4*)(X + (long)b*PERB) + (long)chunk*8192 + threadIdx.x;
    float s = 0.f, q = 0.f;
    for (int k = 0; k < 32; k++) {
        float4 v = p[(long)k*256];
        s += v.x + v.y + v.z + v.w;
        q += v.x*v.x + v.y*v.y + v.z*v.z + v.w*v.w;
    }
    __shared__ float rs[256], rq[256];
    rs[threadIdx.x] = s; rq[threadIdx.x] = q; __syncthreads();
    for (int st = 128; st > 0; st >>= 1) {
        if (threadIdx.x < st) {
            rs[threadIdx.x] += rs[threadIdx.x + st];
            rq[threadIdx.x] += rq[threadIdx.x + st];
        }
        __syncthreads();
    }
    if (threadIdx.x == 0) {
        part[(b*32 + chunk)*2]     = rs[0];
        part[(b*32 + chunk)*2 + 1] = rq[0];
    }
}

__global__ void ln_final(const float* __restrict__ part, float* __restrict__ stat)
{
    int b = blockIdx.x;
    float s = part[(b*32 + threadIdx.x)*2];
    float q = part[(b*32 + threadIdx.x)*2 + 1];
    for (int o = 16; o > 0; o >>= 1) {
        s += __shfl_down_sync(0xffffffffu, s, o);
        q += __shfl_down_sync(0xffffffffu, q, o);
    }
    if (threadIdx.x == 0) {
        float mean = s / (float)PERB;
        float var  = q / (float)PERB - mean * mean;
        stat[b*2] = mean; stat[b*2 + 1] = rsqrtf(var + 1e-5f);
    }
}

__global__ void ln_apply(const float* __restrict__ X, const float* __restrict__ g,
                         const float* __restrict__ bt, const float* __restrict__ stat,
                         float* __restrict__ out, bf16* __restrict__ oh,
                         bf16* __restrict__ ol)
{
    long i4  = (long)blockIdx.x * blockDim.x + threadIdx.x;
    long idx = i4 * 4;
    int  b   = (int)(idx / PERB);
    long gi  = idx % PERB;
    float mean = stat[b*2], rstd = stat[b*2 + 1];
    float4 x  = *(const float4*)(X + idx);
    float4 gg = *(const float4*)(g + gi);
    float4 bb = *(const float4*)(bt + gi);
    float4 o;
    o.x = (x.x - mean) * rstd * gg.x + bb.x;
    o.y = (x.y - mean) * rstd * gg.y + bb.y;
    o.z = (x.z - mean) * rstd * gg.z + bb.z;
    o.w = (x.w - mean) * rstd * gg.w + bb.w;
    *(float4*)(out + idx) = o;
    if (oh) {
        float v[4] = {o.x, o.y, o.z, o.w};
        bf16 h[4], l[4];
        #pragma unroll
        for (int k = 0; k < 4; k++) {
            h[k] = __float2bfloat16(v[k]);
            l[k] = __float2bfloat16(v[k] - __bfloat162float(h[k]));
        }
        ((uint2*)oh)[i4] = *(uint2*)h;
        ((uint2*)ol)[i4] = *(uint2*)l;
    }
}

// ---------------- host orchestration ----------------
#define GS(BM, BN) (2*((BM)+(BN))*128)

extern "C" void kernel_launch(void* const* d_in, const int* in_sizes, int n_in,
                              void* d_out, int out_size)
{
    (void)in_sizes; (void)n_in; (void)out_size;
    const float* mem   = (const float*)d_in[0];
    const float* y_in  = (const float*)d_in[1];
    const float* Wq_sa = (const float*)d_in[2];
    const float* bq_sa = (const float*)d_in[3];
    const float* Wk_sa = (const float*)d_in[4];
    const float* bk_sa = (const float*)d_in[5];
    const float* Wv_sa = (const float*)d_in[6];
    const float* bv_sa = (const float*)d_in[7];
    const float* Wo_sa = (const float*)d_in[8];
    const float* bo_sa = (const float*)d_in[9];
    const float* Wq_x  = (const float*)d_in[10];
    const float* bq_x  = (const float*)d_in[11];
    const float* Wk_x  = (const float*)d_in[12];
    const float* bk_x  = (const float*)d_in[13];
    const float* Wv_x  = (const float*)d_in[14];
    const float* bv_x  = (const float*)d_in[15];
    const float* Wo_x  = (const float*)d_in[16];
    const float* bo_x  = (const float*)d_in[17];
    const float* E1    = (const float*)d_in[18];
    const float* D1    = (const float*)d_in[19];
    const float* E2    = (const float*)d_in[20];
    const float* D2    = (const float*)d_in[21];
    const float* g1    = (const float*)d_in[22];
    const float* b1    = (const float*)d_in[23];
    const float* g2    = (const float*)d_in[24];
    const float* b2    = (const float*)d_in[25];
    const float* g3    = (const float*)d_in[26];
    const float* b3    = (const float*)d_in[27];
    float* out = (float*)d_out;

    float *yp,*qkv,*qx,*kv,*wp,*bp,*pm,*pz,*qm,*qz,*km,*kz,*bm,*bmp,*part,*stat,*wk;
    bf16 *ah,*al,*bh,*bl,*zh,*zl,*hh,*hl,*w1h,*w1l,*w2h,*w2l;
    cudaGetSymbolAddress((void**)&yp,   g_y);
    cudaGetSymbolAddress((void**)&qkv,  g_qkv);
    cudaGetSymbolAddress((void**)&qx,   g_qx);
    cudaGetSymbolAddress((void**)&kv,   g_kv);
    cudaGetSymbolAddress((void**)&wp,   g_wp);
    cudaGetSymbolAddress((void**)&bp,   g_bp);
    cudaGetSymbolAddress((void**)&pm,   g_pm);
    cudaGetSymbolAddress((void**)&pz,   g_pz);
    cudaGetSymbolAddress((void**)&qm,   g_qm);
    cudaGetSymbolAddress((void**)&qz,   g_qz);
    cudaGetSymbolAddress((void**)&km,   g_km);
    cudaGetSymbolAddress((void**)&kz,   g_kz);
    cudaGetSymbolAddress((void**)&bm,   g_bm);
    cudaGetSymbolAddress((void**)&bmp,  g_bmp);
    cudaGetSymbolAddress((void**)&part, g_part);
    cudaGetSymbolAddress((void**)&stat, g_stat);
    cudaGetSymbolAddress((void**)&wk,   g_wk);
    cudaGetSymbolAddress((void**)&ah,   g_ah);
    cudaGetSymbolAddress((void**)&al,   g_al);
    cudaGetSymbolAddress((void**)&bh,   g_bh);
    cudaGetSymbolAddress((void**)&bl,   g_bl);
    cudaGetSymbolAddress((void**)&zh,   g_zh);
    cudaGetSymbolAddress((void**)&zl,   g_zl);
    cudaGetSymbolAddress((void**)&hh,   g_hh);
    cudaGetSymbolAddress((void**)&hl,   g_hl);
    cudaGetSymbolAddress((void**)&w1h,  g_w1h);
    cudaGetSymbolAddress((void**)&w1l,  g_w1l);
    cudaGetSymbolAddress((void**)&w2h,  g_w2h);
    cudaGetSymbolAddress((void**)&w2l,  g_w2l);

    cudaFuncSetAttribute(mma_gemm<128,128,64,32,0>,
        cudaFuncAttributeMaxDynamicSharedMemorySize, GS(128,128));
    cudaFuncSetAttribute(mma_gemm<128,128,64,32,1>,
        cudaFuncAttributeMaxDynamicSharedMemorySize, GS(128,128));
    cudaFuncSetAttribute(mma_gemm<64,64,32,32,2>,
        cudaFuncAttributeMaxDynamicSharedMemorySize, GS(64,64));

    // ===== LFFN fused-weight prep (split-K) =====
    tsplit<<<dim3(ST/32, DHI/32), dim3(32,8)>>>(D1, ST, DHI, ah, al);
    splitf<<<DDIM*ST/8/256, 256>>>(E1, bh, bl, DDIM*ST/8);
    mma_gemm<64,64,32,32,2><<<dim3(DDIM/64, DHI/64, 8), 128, GS(64,64)>>>(
        ah, al, bh, bl, ST/8, ST, wk, nullptr, nullptr, DDIM, nullptr, nullptr, 0);
    wreduce<<<(DHI*DDIM + 255)/256, 256>>>(wk, (long)DHI*DDIM, 8, w1h, w1l, (long)DHI*DDIM);
    tsplit<<<dim3(ST/32, DDIM/32), dim3(32,8)>>>(D2, ST, DDIM, ah, al);
    splitf<<<DHI*ST/8/256, 256>>>(E2, bh, bl, DHI*ST/8);
    mma_gemm<64,64,32,32,2><<<dim3(DHI/64, DDIM/64, 8), 128, GS(64,64)>>>(
        ah, al, bh, bl, ST/8, ST, wk, nullptr, nullptr, DHI, nullptr, nullptr, 0);
    wreduce<<<(DDIM*DHI + 255)/256, 256>>>(wk, (long)DDIM*DHI, 8, w2h, w2l, (long)DDIM*DHI);

    // ===== masked self-attention =====
    pack_qkv<<<(DDIM*384 + 255)/256, 256>>>(Wq_sa, Wk_sa, Wv_sa, bq_sa, bk_sa, bv_sa, wp, bp);
    tsplit<<<dim3(DDIM/32, 384/32), dim3(32,8)>>>(wp, DDIM, 384, bh, bl);
    splitf<<<TOK*DDIM/8/256, 256>>>(y_in, ah, al, TOK*DDIM/8);
    mma_gemm<128,128,64,32,0><<<dim3(3, TOK/128), 256, GS(128,128)>>>(
        ah, al, bh, bl, DDIM, DDIM, qkv, nullptr, nullptr, 384, bp, nullptr, 0);
    colpart<<<dim3(8, BB), 256>>>(qkv, 384,   0, ST, 1, pm, pz);
    colmerge<<<BB, 128>>>(pm, pz, qm, qz);
    colpart<<<dim3(8, BB), 256>>>(qkv, 384, 128, ST, 0, pm, pz);
    colmerge<<<BB, 128>>>(pm, pz, km, kz);
    bmpart<<<dim3(8, 16), 256>>>(qkv, 384, 128, qkv, 384, 256, ST, km, bmp);
    bm_reduce<<<16*4096/256, 256>>>(bmp, kz, bm);
    z_kernel<<<TOK/16, 256>>>(qkv, 384, bm, qm, qz, zh, zl, 1);
    tsplit<<<dim3(128/32, DDIM/32), dim3(32,8)>>>(Wo_sa, 128, DDIM, bh, bl);
    mma_gemm<128,128,64,32,0><<<dim3(4, TOK/128), 256, GS(128,128)>>>(
        zh, zl, bh, bl, 128, 128, yp, nullptr, nullptr, DDIM, bo_sa, y_in, 0);
    ln_part<<<dim3(32, BB), 256>>>(yp, part);
    ln_final<<<BB, 32>>>(part, stat);
    ln_apply<<<TOK*DDIM/4/256, 256>>>(yp, g1, b1, stat, yp, ah, al);

    // ===== cross-attention =====
    pack_qkv<<<(DDIM*384 + 255)/256, 256>>>(Wq_x, Wk_x, Wv_x, bq_x, bk_x, bv_x, wp, bp);
    tsplit<<<dim3(DDIM/32, 384/32), dim3(32,8)>>>(wp, DDIM, 384, bh, bl);
    mma_gemm<128,128,64,32,0><<<dim3(1, TOK/128), 256, GS(128,128)>>>(
        ah, al, bh, bl, DDIM, DDIM, qx, nullptr, nullptr, 128, bp, nullptr, 0);
    splitf<<<TOKM*DDIM/8/256, 256>>>(mem, ah, al, TOKM*DDIM/8);
    mma_gemm<128,128,64,32,0><<<dim3(2, TOKM/128), 256, GS(128,128)>>>(
        ah, al, bh + 128*DDIM, bl + 128*DDIM, DDIM, DDIM, kv, nullptr, nullptr,
        256, bp + 128, nullptr, 0);
    colpart<<<dim3(8, BB), 256>>>(qx, 128, 0, ST,  0, pm, pz);
    colmerge<<<BB, 128>>>(pm, pz, qm, qz);
    colpart<<<dim3(8, BB), 256>>>(kv, 256, 0, SMM, 0, pm, pz);
    colmerge<<<BB, 128>>>(pm, pz, km, kz);
    bmpart<<<dim3(8, 16), 256>>>(kv, 256, 0, kv, 256, 128, SMM, km, bmp);
    bm_reduce<<<16*4096/256, 256>>>(bmp, kz, bm);
    z_kernel<<<TOK/16, 256>>>(qx, 128, bm, qm, qz, zh, zl, 0);
    tsplit<<<dim3(128/32, DDIM/32), dim3(32,8)>>>(Wo_x, 128, DDIM, bh, bl);
    mma_gemm<128,128,64,32,0><<<dim3(4, TOK/128), 256, GS(128,128)>>>(
        zh, zl, bh, bl, 128, 128, yp, nullptr, nullptr, DDIM, bo_x, yp, 0);
    ln_part<<<dim3(32, BB), 256>>>(yp, part);
    ln_final<<<BB, 32>>>(part, stat);
    ln_apply<<<TOK*DDIM/4/256, 256>>>(yp, g2, b2, stat, yp, ah, al);

    // ===== LFFN =====
    mma_gemm<128,128,64,32,1><<<dim3(DHI/128, TOK/128), 256, GS(128,128)>>>(
        ah, al, w1h, w1l, DDIM, DDIM, nullptr, hh, hl, DHI, nullptr, nullptr, 1);
    mma_gemm<128,128,64,32,0><<<dim3(4, TOK/128), 256, GS(128,128)>>>(
        hh, hl, w2h, w2l, DHI, DHI, yp, nullptr, nullptr, DDIM, nullptr, yp, 0);
    ln_part<<<dim3(32, BB), 256>>>(yp, part);
    ln_final<<<BB, 32>>>(part, stat);
    ln_apply<<<TOK*DDIM/4/256, 256>>>(yp, g3, b3, stat, out, nullptr, nullptr);
}